// round 2
// baseline (speedup 1.0000x reference)
#include <cuda_runtime.h>

// TensorTrainLinear: out = x @ W + bias, where W (4096x4096) is materialized
// from the three TT cores each launch (deterministic, allocation-free).
//
// Inputs (metadata order):
//   d_in[0] x     f32 [2,1024,4096]  -> treated as [M=2048, 4096]
//   d_in[1] core0 f32 [1,16,16,16]   (i1, o1, q)
//   d_in[2] core1 f32 [16,16,16,16]  (q, i2, o2, r)
//   d_in[3] core2 f32 [16,16,16,1]   (r, i3, o3)
//   d_in[4] bias  f32 [4096]
// Output: f32 [2048, 4096]

#define KDIM 4096
#define NDIM 4096

// Scratch (device globals; no runtime allocation allowed)
__device__ float g_M01[16 * 16 * 16 * 16 * 16]; // [i1][o1][i2][o2][r]  (4 MB)
__device__ float g_W[(size_t)KDIM * NDIM];      // [in][out]            (64 MB)

// ---------------------------------------------------------------------------
// Stage 1: M01[i1,o1,i2,o2,r] = sum_q core0[i1,o1,q] * core1[q,i2,o2,r]
// ---------------------------------------------------------------------------
__global__ void tt_stage1(const float* __restrict__ core0,
                          const float* __restrict__ core1) {
    __shared__ float s_c0[4096];
    const int tid = threadIdx.x;
#pragma unroll
    for (int i = 0; i < 16; ++i) s_c0[tid + i * 256] = core0[tid + i * 256];
    __syncthreads();

    const int e  = blockIdx.x * 256 + tid;   // flat index == M01 layout
    const int r  = e & 15;
    const int o2 = (e >> 4) & 15;
    const int i2 = (e >> 8) & 15;
    const int o1 = (e >> 12) & 15;
    const int i1 = (e >> 16) & 15;

    const float* c0p = s_c0 + i1 * 256 + o1 * 16;            // stride 1 over q
    const float* c1p = core1 + i2 * 256 + o2 * 16 + r;       // stride 4096 over q
    float acc = 0.f;
#pragma unroll
    for (int q = 0; q < 16; ++q)
        acc = fmaf(c0p[q], c1p[q * 4096], acc);
    g_M01[e] = acc;
}

// ---------------------------------------------------------------------------
// Stage 2: W[in, o] = sum_r M01[i1,o1,i2,o2,r] * core2[r,i3,o3]
//          in = i1*256 + i2*16 + i3 ; o = o1*256 + o2*16 + o3
// ---------------------------------------------------------------------------
__global__ void tt_stage2(const float* __restrict__ core2) {
    __shared__ float s_c2[4096];
    const int tid = threadIdx.x;
#pragma unroll
    for (int i = 0; i < 16; ++i) s_c2[tid + i * 256] = core2[tid + i * 256];
    __syncthreads();

    const unsigned idx = blockIdx.x * 256u + tid;  // 0 .. 16777215
    const int o  = idx & 4095;
    const int in = idx >> 12;
    const int o3 = o & 15, o2 = (o >> 4) & 15, o1 = o >> 8;
    const int i3 = in & 15, i2 = (in >> 4) & 15, i1 = in >> 8;

    const float* m = g_M01 + ((((i1 * 16 + o1) * 16 + i2) * 16 + o2) * 16);
    float acc = 0.f;
#pragma unroll
    for (int r = 0; r < 16; ++r)
        acc = fmaf(m[r], s_c2[r * 256 + i3 * 16 + o3], acc);
    g_W[idx] = acc;
}

// ---------------------------------------------------------------------------
// GEMM: out[M,4096] = x[M,4096] @ g_W[4096,4096] + bias
// 128x128 block tile, BK=16, 256 threads, 8x8 per thread, double-buffered smem
// ---------------------------------------------------------------------------
__global__ __launch_bounds__(256) void tt_gemm(const float* __restrict__ A,
                                               const float* __restrict__ bias,
                                               float* __restrict__ out) {
    __shared__ float As[2][16][128];  // [k][m]
    __shared__ float Bs[2][16][128];  // [k][n]

    const int tid = threadIdx.x;
    const int bm = blockIdx.y, bn = blockIdx.x;
    const int tm8 = (tid >> 4) * 8;  // row sub-tile base
    const int tn8 = (tid & 15) * 8;  // col sub-tile base

    const float* Ab = A + (size_t)bm * 128 * KDIM;
    const float* Bb = g_W + (size_t)bn * 128;

    // A loader: thread -> (row = tid>>1, k offset = (tid&1)*8), 8 floats
    const int aRow = tid >> 1;
    const int aK   = (tid & 1) * 8;
    // B loader: thread -> (k row = tid>>4, col = (tid&15)*8), 8 floats
    const int bRow = tid >> 4;
    const int bCol = (tid & 15) * 8;

    float acc[8][8];
#pragma unroll
    for (int i = 0; i < 8; ++i)
#pragma unroll
        for (int j = 0; j < 8; ++j) acc[i][j] = 0.f;

    float4 a0, a1, b0, b1;

    // Prologue: load tile kt=0 into buffer 0
    {
        const float* pa = Ab + (size_t)aRow * KDIM + aK;
        a0 = *(const float4*)pa;
        a1 = *(const float4*)(pa + 4);
        const float* pb = Bb + (size_t)bRow * NDIM + bCol;
        b0 = *(const float4*)pb;
        b1 = *(const float4*)(pb + 4);
        As[0][aK + 0][aRow] = a0.x; As[0][aK + 1][aRow] = a0.y;
        As[0][aK + 2][aRow] = a0.z; As[0][aK + 3][aRow] = a0.w;
        As[0][aK + 4][aRow] = a1.x; As[0][aK + 5][aRow] = a1.y;
        As[0][aK + 6][aRow] = a1.z; As[0][aK + 7][aRow] = a1.w;
        *(float4*)&Bs[0][bRow][bCol]     = b0;
        *(float4*)&Bs[0][bRow][bCol + 4] = b1;
    }
    __syncthreads();

    int buf = 0;
    const int KT = KDIM / 16;  // 256
    for (int kt = 0; kt < KT; ++kt) {
        if (kt + 1 < KT) {
            const float* pa = Ab + (size_t)aRow * KDIM + (kt + 1) * 16 + aK;
            a0 = *(const float4*)pa;
            a1 = *(const float4*)(pa + 4);
            const float* pb = Bb + (size_t)((kt + 1) * 16 + bRow) * NDIM + bCol;
            b0 = *(const float4*)pb;
            b1 = *(const float4*)(pb + 4);
        }

#pragma unroll
        for (int kk = 0; kk < 16; ++kk) {
            float af[8], bf[8];
#pragma unroll
            for (int j = 0; j < 8; ++j) {
                af[j] = As[buf][kk][tm8 + j];
                bf[j] = Bs[buf][kk][tn8 + j];
            }
#pragma unroll
            for (int i = 0; i < 8; ++i)
#pragma unroll
                for (int j = 0; j < 8; ++j)
                    acc[i][j] = fmaf(af[i], bf[j], acc[i][j]);
        }

        if (kt + 1 < KT) {
            const int nb = buf ^ 1;
            As[nb][aK + 0][aRow] = a0.x; As[nb][aK + 1][aRow] = a0.y;
            As[nb][aK + 2][aRow] = a0.z; As[nb][aK + 3][aRow] = a0.w;
            As[nb][aK + 4][aRow] = a1.x; As[nb][aK + 5][aRow] = a1.y;
            As[nb][aK + 6][aRow] = a1.z; As[nb][aK + 7][aRow] = a1.w;
            *(float4*)&Bs[nb][bRow][bCol]     = b0;
            *(float4*)&Bs[nb][bRow][bCol + 4] = b1;
            __syncthreads();
            buf = nb;
        }
    }

    // Epilogue: add bias, vectorized stores
    const float* bp = bias + bn * 128 + tn8;
    float bv[8];
#pragma unroll
    for (int j = 0; j < 8; ++j) bv[j] = bp[j];

#pragma unroll
    for (int i = 0; i < 8; ++i) {
        const int row = bm * 128 + tm8 + i;
        float* op = out + (size_t)row * NDIM + bn * 128 + tn8;
        float4 v;
        v.x = acc[i][0] + bv[0]; v.y = acc[i][1] + bv[1];
        v.z = acc[i][2] + bv[2]; v.w = acc[i][3] + bv[3];
        *(float4*)op = v;
        v.x = acc[i][4] + bv[4]; v.y = acc[i][5] + bv[5];
        v.z = acc[i][6] + bv[6]; v.w = acc[i][7] + bv[7];
        *(float4*)(op + 4) = v;
    }
}

extern "C" void kernel_launch(void* const* d_in, const int* in_sizes, int n_in,
                              void* d_out, int out_size) {
    const float* x     = (const float*)d_in[0];
    const float* core0 = (const float*)d_in[1];
    const float* core1 = (const float*)d_in[2];
    const float* core2 = (const float*)d_in[3];
    const float* bias  = (const float*)d_in[4];
    float* out = (float*)d_out;

    const int M = in_sizes[0] / KDIM;  // 2048

    // Build W from TT cores (runs every launch — deterministic, tiny cost)
    tt_stage1<<<4096, 256>>>(core0, core1);
    tt_stage2<<<65536, 256>>>(core2);

    // Dense GEMM + bias
    dim3 grid(NDIM / 128, M / 128);  // (32, 16)
    tt_gemm<<<grid, 256>>>(x, bias, out);
}

// round 4
// speedup vs baseline: 2.2691x; 2.2691x over previous
#include <cuda_runtime.h>
#include <cuda_bf16.h>
#include <cstdint>

// TensorTrainLinear: out = x @ W + bias.
// W (4096x4096) materialized from TT cores each launch; x and W split into
// bf16 hi/lo; GEMM = mma.sync m16n8k16 bf16 with 3 compensated products
// (hi*hi + hi*lo + lo*hi) accumulated in fp32 fragments.
// (tcgen05 is rejected by this bench's compute_100 PTX target — use the
//  sm_80+ mma.sync path, which still drives Blackwell tensor cores.)

#define KDIM 4096
#define NDIM 4096
#define MDIM 2048

// ---- device scratch (no runtime allocation allowed) ----
__device__ float         g_M01[16 * 16 * 16 * 16 * 16];      // 4 MB
__device__ __nv_bfloat16 g_xhi[(size_t)MDIM * KDIM];          // 16 MB
__device__ __nv_bfloat16 g_xlo[(size_t)MDIM * KDIM];          // 16 MB
__device__ __nv_bfloat16 g_wthi[(size_t)NDIM * KDIM];         // 32 MB  [o][in]
__device__ __nv_bfloat16 g_wtlo[(size_t)NDIM * KDIM];         // 32 MB  [o][in]

// ---------------------------------------------------------------------------
// helpers
// ---------------------------------------------------------------------------
__device__ __forceinline__ uint32_t smem_u32(const void* p) {
    uint32_t a;
    asm("{ .reg .u64 t; cvta.to.shared.u64 t, %1; cvt.u32.u64 %0, t; }"
        : "=r"(a) : "l"(p));
    return a;
}

__device__ __forceinline__ void cp16(uint32_t saddr, const void* gaddr) {
    asm volatile("cp.async.cg.shared.global [%0], [%1], 16;\n"
                 :: "r"(saddr), "l"(gaddr));
}
__device__ __forceinline__ void cp_commit() {
    asm volatile("cp.async.commit_group;\n" ::: "memory");
}

__device__ __forceinline__ void ldm4(uint32_t& r0, uint32_t& r1,
                                     uint32_t& r2, uint32_t& r3,
                                     uint32_t addr) {
    asm volatile("ldmatrix.sync.aligned.m8n8.x4.shared.b16 {%0,%1,%2,%3}, [%4];"
                 : "=r"(r0), "=r"(r1), "=r"(r2), "=r"(r3) : "r"(addr));
}

__device__ __forceinline__ void mma16816(float* c, const uint32_t* a,
                                         const uint32_t* b) {
    asm volatile(
        "mma.sync.aligned.m16n8k16.row.col.f32.bf16.bf16.f32 "
        "{%0,%1,%2,%3}, {%4,%5,%6,%7}, {%8,%9}, {%0,%1,%2,%3};"
        : "+f"(c[0]), "+f"(c[1]), "+f"(c[2]), "+f"(c[3])
        : "r"(a[0]), "r"(a[1]), "r"(a[2]), "r"(a[3]), "r"(b[0]), "r"(b[1]));
}

// ---------------------------------------------------------------------------
// x -> bf16 hi/lo split
// ---------------------------------------------------------------------------
__global__ __launch_bounds__(256) void cvt_x(const float* __restrict__ x) {
    const size_t base = ((size_t)blockIdx.x * 256 + threadIdx.x) * 8;
    float4 v0 = *(const float4*)(x + base);
    float4 v1 = *(const float4*)(x + base + 4);
    float f[8] = {v0.x, v0.y, v0.z, v0.w, v1.x, v1.y, v1.z, v1.w};
    __nv_bfloat16 hi[8], lo[8];
#pragma unroll
    for (int i = 0; i < 8; ++i) {
        hi[i] = __float2bfloat16(f[i]);
        lo[i] = __float2bfloat16(f[i] - __bfloat162float(hi[i]));
    }
    *(uint4*)(g_xhi + base) = *(uint4*)hi;
    *(uint4*)(g_xlo + base) = *(uint4*)lo;
}

// ---------------------------------------------------------------------------
// Stage 1: M01[i1,o1,i2,o2,r] = sum_q core0[i1,o1,q] * core1[q,i2,o2,r]
// ---------------------------------------------------------------------------
__global__ void tt_stage1(const float* __restrict__ core0,
                          const float* __restrict__ core1) {
    __shared__ float s_c0[4096];
    const int tid = threadIdx.x;
#pragma unroll
    for (int i = 0; i < 16; ++i) s_c0[tid + i * 256] = core0[tid + i * 256];
    __syncthreads();

    const int e  = blockIdx.x * 256 + tid;
    const int r  = e & 15;
    const int o2 = (e >> 4) & 15;
    const int i2 = (e >> 8) & 15;
    const int o1 = (e >> 12) & 15;
    const int i1 = (e >> 16) & 15;

    const float* c0p = s_c0 + i1 * 256 + o1 * 16;
    const float* c1p = core1 + i2 * 256 + o2 * 16 + r;
    float acc = 0.f;
#pragma unroll
    for (int q = 0; q < 16; ++q)
        acc = fmaf(c0p[q], c1p[q * 4096], acc);
    g_M01[e] = acc;
}

// ---------------------------------------------------------------------------
// Stage 2 (transposed output): Wt[o][in] as bf16 hi/lo split.
// ---------------------------------------------------------------------------
__global__ __launch_bounds__(256) void tt_stage2t(const float* __restrict__ core2) {
    __shared__ float s_c2t[4096];  // [r][o3][i3]
    const int tid = threadIdx.x;
#pragma unroll
    for (int i = 0; i < 16; ++i) {
        const int idx = tid + i * 256;          // src = r*256 + i3*16 + o3
        const int r = idx >> 8, i3 = (idx >> 4) & 15, o3 = idx & 15;
        s_c2t[r * 256 + o3 * 16 + i3] = core2[idx];
    }
    __syncthreads();

    const unsigned g = blockIdx.x * 256u + tid;   // 0 .. 2^20-1
    const int in  = g & 4095;
    const int ohi = g >> 12;                      // o1*16 + o2
    const int o1 = ohi >> 4, o2 = ohi & 15;
    const int i1 = in >> 8, i2 = (in >> 4) & 15, i3 = in & 15;

    const float* m = g_M01 + ((((i1 * 16 + o1) * 16 + i2) * 16 + o2) << 4);
    float m01[16];
#pragma unroll
    for (int r4 = 0; r4 < 4; ++r4) {
        float4 v = ((const float4*)m)[r4];
        m01[r4 * 4 + 0] = v.x; m01[r4 * 4 + 1] = v.y;
        m01[r4 * 4 + 2] = v.z; m01[r4 * 4 + 3] = v.w;
    }

#pragma unroll
    for (int o3 = 0; o3 < 16; ++o3) {
        float acc = 0.f;
#pragma unroll
        for (int r = 0; r < 16; ++r)
            acc = fmaf(m01[r], s_c2t[r * 256 + o3 * 16 + i3], acc);
        const __nv_bfloat16 h = __float2bfloat16(acc);
        const __nv_bfloat16 l = __float2bfloat16(acc - __bfloat162float(h));
        const size_t off = (size_t)(ohi * 16 + o3) * KDIM + in;
        g_wthi[off] = h;
        g_wtlo[off] = l;
    }
}

// ---------------------------------------------------------------------------
// GEMM: out[2048,4096] = x @ W + bias via mma.sync bf16x3
// CTA 128x128, BK=32, 8 warps (2x4), warp tile 64x32.
// Smem rows: 32 bf16 = 64B data + 16B pad = 80B stride (conflict-free ldmatrix).
// ---------------------------------------------------------------------------
#define ROWB       80
#define TILE_BYTES (128 * ROWB)     // 10240
#define BUF_BYTES  (4 * TILE_BYTES) // 40960 (Ahi, Alo, Bhi, Blo)
#define SMEM_TOTAL (2 * BUF_BYTES)  // 81920

__device__ __forceinline__ void load_chunk(uint32_t sb, int buf, int c,
                                           int bm, int bn, int tid) {
    const __nv_bfloat16* bases[4] = {
        g_xhi  + ((size_t)bm * 128) * KDIM + (size_t)c * 32,
        g_xlo  + ((size_t)bm * 128) * KDIM + (size_t)c * 32,
        g_wthi + ((size_t)bn * 128) * KDIM + (size_t)c * 32,
        g_wtlo + ((size_t)bn * 128) * KDIM + (size_t)c * 32,
    };
#pragma unroll
    for (int t = 0; t < 4; ++t) {
        const uint32_t ts = sb + buf * BUF_BYTES + t * TILE_BYTES;
        const char* gb = (const char*)bases[t];
#pragma unroll
        for (int i = 0; i < 2; ++i) {
            const int e   = tid + i * 256;   // 0..511
            const int row = e >> 2;          // 0..127
            const int seg = e & 3;           // 16B segment
            cp16(ts + row * ROWB + seg * 16,
                 gb + (size_t)row * (KDIM * 2) + seg * 16);
        }
    }
    cp_commit();
}

__global__ void __launch_bounds__(256, 1)
tt_gemm_mma(const float* __restrict__ bias, float* __restrict__ out) {
    extern __shared__ __align__(128) char smem[];
    const uint32_t sb = smem_u32(smem);
    const int tid = threadIdx.x;
    const int lane = tid & 31;
    const int wid = tid >> 5;
    const int warpM = wid >> 2;      // 0..1
    const int warpN = wid & 3;       // 0..3
    const int bn = blockIdx.x, bm = blockIdx.y;

    float acc[4][4][4];
#pragma unroll
    for (int i = 0; i < 4; ++i)
#pragma unroll
        for (int j = 0; j < 4; ++j)
#pragma unroll
            for (int k = 0; k < 4; ++k) acc[i][j][k] = 0.f;

    // ldmatrix lane offsets (within tile)
    const uint32_t aoff =
        (uint32_t)(warpM * 64 + (lane & 15)) * ROWB + ((lane >> 4) << 4);
    const uint32_t boff =
        (uint32_t)(warpN * 32 + (lane & 7) + ((lane >> 4) & 1) * 8) * ROWB +
        (((lane >> 3) & 1) << 4);

    load_chunk(sb, 0, 0, bm, bn, tid);
    load_chunk(sb, 1, 1, bm, bn, tid);

    const int KT = KDIM / 32;  // 128
    for (int c = 0; c < KT; ++c) {
        const int b = c & 1;
        if (c < KT - 2) asm volatile("cp.async.wait_group 1;" ::: "memory");
        else            asm volatile("cp.async.wait_group 0;" ::: "memory");
        __syncthreads();

        const uint32_t sA  = sb + b * BUF_BYTES;
        const uint32_t sAl = sA + TILE_BYTES;
        const uint32_t sB  = sA + 2 * TILE_BYTES;
        const uint32_t sBl = sA + 3 * TILE_BYTES;

#pragma unroll
        for (int ks = 0; ks < 2; ++ks) {
            const uint32_t ko = ks * 32;  // 16 bf16 = 32B
            uint32_t ah[4][4], al[4][4], bh[4][2], bl[4][2];
#pragma unroll
            for (int mt = 0; mt < 4; ++mt) {
                const uint32_t mo = mt * 16 * ROWB + ko;
                ldm4(ah[mt][0], ah[mt][1], ah[mt][2], ah[mt][3], sA  + aoff + mo);
                ldm4(al[mt][0], al[mt][1], al[mt][2], al[mt][3], sAl + aoff + mo);
            }
#pragma unroll
            for (int np = 0; np < 2; ++np) {
                const uint32_t no = np * 16 * ROWB + ko;
                uint32_t r0, r1, r2, r3;
                ldm4(r0, r1, r2, r3, sB + boff + no);
                bh[np * 2][0] = r0; bh[np * 2][1] = r1;
                bh[np * 2 + 1][0] = r2; bh[np * 2 + 1][1] = r3;
                ldm4(r0, r1, r2, r3, sBl + boff + no);
                bl[np * 2][0] = r0; bl[np * 2][1] = r1;
                bl[np * 2 + 1][0] = r2; bl[np * 2 + 1][1] = r3;
            }
#pragma unroll
            for (int mt = 0; mt < 4; ++mt)
#pragma unroll
                for (int nt = 0; nt < 4; ++nt) {
                    mma16816(acc[mt][nt], ah[mt], bh[nt]);
                    mma16816(acc[mt][nt], ah[mt], bl[nt]);
                    mma16816(acc[mt][nt], al[mt], bh[nt]);
                }
        }

        __syncthreads();
        if (c + 2 < KT) load_chunk(sb, b, c + 2, bm, bn, tid);
    }

    // Epilogue: c-frag layout m16n8: lane -> rows l/4, l/4+8; cols 2*(l%4)
    const int rbase = bm * 128 + warpM * 64 + (lane >> 2);
    const int cbase = bn * 128 + warpN * 32 + (lane & 3) * 2;
#pragma unroll
    for (int nt = 0; nt < 4; ++nt) {
        const int col = cbase + nt * 8;
        const float b0 = bias[col], b1 = bias[col + 1];
#pragma unroll
        for (int mt = 0; mt < 4; ++mt) {
            const int row = rbase + mt * 16;
            float2 v0 = make_float2(acc[mt][nt][0] + b0, acc[mt][nt][1] + b1);
            float2 v1 = make_float2(acc[mt][nt][2] + b0, acc[mt][nt][3] + b1);
            *(float2*)(out + (size_t)row * NDIM + col) = v0;
            *(float2*)(out + (size_t)(row + 8) * NDIM + col) = v1;
        }
    }
}

// ---------------------------------------------------------------------------
extern "C" void kernel_launch(void* const* d_in, const int* in_sizes, int n_in,
                              void* d_out, int out_size) {
    const float* x     = (const float*)d_in[0];
    const float* core0 = (const float*)d_in[1];
    const float* core1 = (const float*)d_in[2];
    const float* core2 = (const float*)d_in[3];
    const float* bias  = (const float*)d_in[4];
    float* out = (float*)d_out;

    cudaFuncSetAttribute(tt_gemm_mma,
                         cudaFuncAttributeMaxDynamicSharedMemorySize,
                         SMEM_TOTAL);

    const int M = in_sizes[0] / KDIM;  // 2048

    cvt_x<<<(M * KDIM) / (256 * 8), 256>>>(x);
    tt_stage1<<<4096, 256>>>(core0, core1);
    tt_stage2t<<<4096, 256>>>(core2);

    dim3 grid(NDIM / 128, M / 128);  // (32, 16)
    tt_gemm_mma<<<grid, 256, SMEM_TOTAL>>>(bias, out);
}

// round 5
// speedup vs baseline: 2.5281x; 1.1141x over previous
#include <cuda_runtime.h>
#include <cuda_bf16.h>
#include <cstdint>

// TensorTrainLinear: out = x @ W + bias.
// W (4096x4096) materialized from TT cores each launch; x and W split into
// bf16 hi/lo; GEMM = mma.sync m16n8k16 bf16 with 3 compensated products
// (hi*hi + hi*lo + lo*hi) accumulated in fp32 fragments.
// R5: 2-CTA/SM residency (launch_bounds(256,2), <=128 regs via restructured
// fragment streaming) to double warp-level latency hiding.

#define KDIM 4096
#define NDIM 4096
#define MDIM 2048

// ---- device scratch (no runtime allocation allowed) ----
__device__ float         g_M01[16 * 16 * 16 * 16 * 16];      // 4 MB
__device__ __nv_bfloat16 g_xhi[(size_t)MDIM * KDIM];          // 16 MB
__device__ __nv_bfloat16 g_xlo[(size_t)MDIM * KDIM];          // 16 MB
__device__ __nv_bfloat16 g_wthi[(size_t)NDIM * KDIM];         // 32 MB  [o][in]
__device__ __nv_bfloat16 g_wtlo[(size_t)NDIM * KDIM];         // 32 MB  [o][in]

// ---------------------------------------------------------------------------
// helpers
// ---------------------------------------------------------------------------
__device__ __forceinline__ uint32_t smem_u32(const void* p) {
    uint32_t a;
    asm("{ .reg .u64 t; cvta.to.shared.u64 t, %1; cvt.u32.u64 %0, t; }"
        : "=r"(a) : "l"(p));
    return a;
}

__device__ __forceinline__ void cp16(uint32_t saddr, const void* gaddr) {
    asm volatile("cp.async.cg.shared.global [%0], [%1], 16;\n"
                 :: "r"(saddr), "l"(gaddr));
}
__device__ __forceinline__ void cp_commit() {
    asm volatile("cp.async.commit_group;\n" ::: "memory");
}

__device__ __forceinline__ void ldm4(uint32_t& r0, uint32_t& r1,
                                     uint32_t& r2, uint32_t& r3,
                                     uint32_t addr) {
    asm volatile("ldmatrix.sync.aligned.m8n8.x4.shared.b16 {%0,%1,%2,%3}, [%4];"
                 : "=r"(r0), "=r"(r1), "=r"(r2), "=r"(r3) : "r"(addr));
}

__device__ __forceinline__ void mma16816(float* c, const uint32_t* a,
                                         const uint32_t* b) {
    asm volatile(
        "mma.sync.aligned.m16n8k16.row.col.f32.bf16.bf16.f32 "
        "{%0,%1,%2,%3}, {%4,%5,%6,%7}, {%8,%9}, {%0,%1,%2,%3};"
        : "+f"(c[0]), "+f"(c[1]), "+f"(c[2]), "+f"(c[3])
        : "r"(a[0]), "r"(a[1]), "r"(a[2]), "r"(a[3]), "r"(b[0]), "r"(b[1]));
}

// ---------------------------------------------------------------------------
// x -> bf16 hi/lo split
// ---------------------------------------------------------------------------
__global__ __launch_bounds__(256) void cvt_x(const float* __restrict__ x) {
    const size_t base = ((size_t)blockIdx.x * 256 + threadIdx.x) * 8;
    float4 v0 = *(const float4*)(x + base);
    float4 v1 = *(const float4*)(x + base + 4);
    float f[8] = {v0.x, v0.y, v0.z, v0.w, v1.x, v1.y, v1.z, v1.w};
    __nv_bfloat16 hi[8], lo[8];
#pragma unroll
    for (int i = 0; i < 8; ++i) {
        hi[i] = __float2bfloat16(f[i]);
        lo[i] = __float2bfloat16(f[i] - __bfloat162float(hi[i]));
    }
    *(uint4*)(g_xhi + base) = *(uint4*)hi;
    *(uint4*)(g_xlo + base) = *(uint4*)lo;
}

// ---------------------------------------------------------------------------
// Stage 1: M01[i1,o1,i2,o2,r] = sum_q core0[i1,o1,q] * core1[q,i2,o2,r]
// ---------------------------------------------------------------------------
__global__ void tt_stage1(const float* __restrict__ core0,
                          const float* __restrict__ core1) {
    __shared__ float s_c0[4096];
    const int tid = threadIdx.x;
#pragma unroll
    for (int i = 0; i < 16; ++i) s_c0[tid + i * 256] = core0[tid + i * 256];
    __syncthreads();

    const int e  = blockIdx.x * 256 + tid;
    const int r  = e & 15;
    const int o2 = (e >> 4) & 15;
    const int i2 = (e >> 8) & 15;
    const int o1 = (e >> 12) & 15;
    const int i1 = (e >> 16) & 15;

    const float* c0p = s_c0 + i1 * 256 + o1 * 16;
    const float* c1p = core1 + i2 * 256 + o2 * 16 + r;
    float acc = 0.f;
#pragma unroll
    for (int q = 0; q < 16; ++q)
        acc = fmaf(c0p[q], c1p[q * 4096], acc);
    g_M01[e] = acc;
}

// ---------------------------------------------------------------------------
// Stage 2 (transposed output): Wt[o][in] as bf16 hi/lo split.
// ---------------------------------------------------------------------------
__global__ __launch_bounds__(256) void tt_stage2t(const float* __restrict__ core2) {
    __shared__ float s_c2t[4096];  // [r][o3][i3]
    const int tid = threadIdx.x;
#pragma unroll
    for (int i = 0; i < 16; ++i) {
        const int idx = tid + i * 256;          // src = r*256 + i3*16 + o3
        const int r = idx >> 8, i3 = (idx >> 4) & 15, o3 = idx & 15;
        s_c2t[r * 256 + o3 * 16 + i3] = core2[idx];
    }
    __syncthreads();

    const unsigned g = blockIdx.x * 256u + tid;   // 0 .. 2^20-1
    const int in  = g & 4095;
    const int ohi = g >> 12;                      // o1*16 + o2
    const int o1 = ohi >> 4, o2 = ohi & 15;
    const int i1 = in >> 8, i2 = (in >> 4) & 15, i3 = in & 15;

    const float* m = g_M01 + ((((i1 * 16 + o1) * 16 + i2) * 16 + o2) << 4);
    float m01[16];
#pragma unroll
    for (int r4 = 0; r4 < 4; ++r4) {
        float4 v = ((const float4*)m)[r4];
        m01[r4 * 4 + 0] = v.x; m01[r4 * 4 + 1] = v.y;
        m01[r4 * 4 + 2] = v.z; m01[r4 * 4 + 3] = v.w;
    }

#pragma unroll
    for (int o3 = 0; o3 < 16; ++o3) {
        float acc = 0.f;
#pragma unroll
        for (int r = 0; r < 16; ++r)
            acc = fmaf(m01[r], s_c2t[r * 256 + o3 * 16 + i3], acc);
        const __nv_bfloat16 h = __float2bfloat16(acc);
        const __nv_bfloat16 l = __float2bfloat16(acc - __bfloat162float(h));
        const size_t off = (size_t)(ohi * 16 + o3) * KDIM + in;
        g_wthi[off] = h;
        g_wtlo[off] = l;
    }
}

// ---------------------------------------------------------------------------
// GEMM: out[2048,4096] = x @ W + bias via mma.sync bf16x3
// CTA 128x128, BK=32, 8 warps (2x4), warp tile 64x32, 2 CTAs/SM.
// Smem rows: 32 bf16 = 64B data + 16B pad = 80B stride (conflict-free ldmatrix).
// ---------------------------------------------------------------------------
#define ROWB       80
#define TILE_BYTES (128 * ROWB)     // 10240
#define BUF_BYTES  (4 * TILE_BYTES) // 40960 (Ahi, Alo, Bhi, Blo)
#define SMEM_TOTAL (2 * BUF_BYTES)  // 81920

__device__ __forceinline__ void load_chunk(uint32_t sb, int buf, int c,
                                           int bm, int bn, int tid) {
    const __nv_bfloat16* bases[4] = {
        g_xhi  + ((size_t)bm * 128) * KDIM + (size_t)c * 32,
        g_xlo  + ((size_t)bm * 128) * KDIM + (size_t)c * 32,
        g_wthi + ((size_t)bn * 128) * KDIM + (size_t)c * 32,
        g_wtlo + ((size_t)bn * 128) * KDIM + (size_t)c * 32,
    };
#pragma unroll
    for (int t = 0; t < 4; ++t) {
        const uint32_t ts = sb + buf * BUF_BYTES + t * TILE_BYTES;
        const char* gb = (const char*)bases[t];
#pragma unroll
        for (int i = 0; i < 2; ++i) {
            const int e   = tid + i * 256;   // 0..511
            const int row = e >> 2;          // 0..127
            const int seg = e & 3;           // 16B segment
            cp16(ts + row * ROWB + seg * 16,
                 gb + (size_t)row * (KDIM * 2) + seg * 16);
        }
    }
    cp_commit();
}

__global__ void __launch_bounds__(256, 2)
tt_gemm_mma(const float* __restrict__ bias, float* __restrict__ out) {
    extern __shared__ __align__(128) char smem[];
    const uint32_t sb = smem_u32(smem);
    const int tid = threadIdx.x;
    const int lane = tid & 31;
    const int wid = tid >> 5;
    const int warpM = wid >> 2;      // 0..1
    const int warpN = wid & 3;       // 0..3
    const int bn = blockIdx.x, bm = blockIdx.y;

    float acc[4][4][4];
#pragma unroll
    for (int i = 0; i < 4; ++i)
#pragma unroll
        for (int j = 0; j < 4; ++j)
#pragma unroll
            for (int k = 0; k < 4; ++k) acc[i][j][k] = 0.f;

    // ldmatrix lane offsets (within tile)
    const uint32_t aoff =
        (uint32_t)(warpM * 64 + (lane & 15)) * ROWB + ((lane >> 4) << 4);
    const uint32_t boff =
        (uint32_t)(warpN * 32 + (lane & 7) + ((lane >> 4) & 1) * 8) * ROWB +
        (((lane >> 3) & 1) << 4);

    load_chunk(sb, 0, 0, bm, bn, tid);
    load_chunk(sb, 1, 1, bm, bn, tid);

    const int KT = KDIM / 32;  // 128
    for (int c = 0; c < KT; ++c) {
        const int b = c & 1;
        if (c < KT - 2) asm volatile("cp.async.wait_group 1;" ::: "memory");
        else            asm volatile("cp.async.wait_group 0;" ::: "memory");
        __syncthreads();

        const uint32_t sA  = sb + b * BUF_BYTES;
        const uint32_t sAl = sA + TILE_BYTES;
        const uint32_t sB  = sA + 2 * TILE_BYTES;
        const uint32_t sBl = sA + 3 * TILE_BYTES;

#pragma unroll
        for (int ks = 0; ks < 2; ++ks) {
            const uint32_t ko = ks * 32;  // 16 bf16 = 32B

            // B fragments for this k-step (held across all mt): 16 regs
            uint32_t bh[4][2], bl[4][2];
#pragma unroll
            for (int np = 0; np < 2; ++np) {
                const uint32_t no = np * 16 * ROWB + ko;
                uint32_t r0, r1, r2, r3;
                ldm4(r0, r1, r2, r3, sB + boff + no);
                bh[np * 2][0] = r0; bh[np * 2][1] = r1;
                bh[np * 2 + 1][0] = r2; bh[np * 2 + 1][1] = r3;
                ldm4(r0, r1, r2, r3, sBl + boff + no);
                bl[np * 2][0] = r0; bl[np * 2][1] = r1;
                bl[np * 2 + 1][0] = r2; bl[np * 2 + 1][1] = r3;
            }

            // Stream A fragments per mt (8 regs live at a time)
#pragma unroll
            for (int mt = 0; mt < 4; ++mt) {
                const uint32_t mo = mt * 16 * ROWB + ko;
                uint32_t ah[4], al[4];
                ldm4(ah[0], ah[1], ah[2], ah[3], sA  + aoff + mo);
                ldm4(al[0], al[1], al[2], al[3], sAl + aoff + mo);
#pragma unroll
                for (int nt = 0; nt < 4; ++nt) {
                    mma16816(acc[mt][nt], ah, bh[nt]);
                    mma16816(acc[mt][nt], ah, bl[nt]);
                    mma16816(acc[mt][nt], al, bh[nt]);
                }
            }
        }

        __syncthreads();
        if (c + 2 < KT) load_chunk(sb, b, c + 2, bm, bn, tid);
    }

    // Epilogue: c-frag layout m16n8: lane -> rows l/4, l/4+8; cols 2*(l%4)
    const int rbase = bm * 128 + warpM * 64 + (lane >> 2);
    const int cbase = bn * 128 + warpN * 32 + (lane & 3) * 2;
#pragma unroll
    for (int nt = 0; nt < 4; ++nt) {
        const int col = cbase + nt * 8;
        const float b0 = bias[col], b1 = bias[col + 1];
#pragma unroll
        for (int mt = 0; mt < 4; ++mt) {
            const int row = rbase + mt * 16;
            float2 v0 = make_float2(acc[mt][nt][0] + b0, acc[mt][nt][1] + b1);
            float2 v1 = make_float2(acc[mt][nt][2] + b0, acc[mt][nt][3] + b1);
            *(float2*)(out + (size_t)row * NDIM + col) = v0;
            *(float2*)(out + (size_t)(row + 8) * NDIM + col) = v1;
        }
    }
}

// ---------------------------------------------------------------------------
extern "C" void kernel_launch(void* const* d_in, const int* in_sizes, int n_in,
                              void* d_out, int out_size) {
    const float* x     = (const float*)d_in[0];
    const float* core0 = (const float*)d_in[1];
    const float* core1 = (const float*)d_in[2];
    const float* core2 = (const float*)d_in[3];
    const float* bias  = (const float*)d_in[4];
    float* out = (float*)d_out;

    cudaFuncSetAttribute(tt_gemm_mma,
                         cudaFuncAttributeMaxDynamicSharedMemorySize,
                         SMEM_TOTAL);

    const int M = in_sizes[0] / KDIM;  // 2048

    cvt_x<<<(M * KDIM) / (256 * 8), 256>>>(x);
    tt_stage1<<<4096, 256>>>(core0, core1);
    tt_stage2t<<<4096, 256>>>(core2);

    dim3 grid(NDIM / 128, M / 128);  // (32, 16)
    tt_gemm_mma<<<grid, 256, SMEM_TOTAL>>>(bias, out);
}

// round 7
// speedup vs baseline: 3.0129x; 1.1917x over previous
#include <cuda_runtime.h>
#include <cuda_bf16.h>
#include <cstdint>

// TensorTrainLinear: out = x @ W + bias.
// W (4096x4096) materialized from TT cores each launch; x and W split into
// bf16 hi/lo; GEMM = mma.sync m16n8k16 bf16 with 3 compensated products
// (hi*hi + hi*lo + lo*hi) accumulated in fp32 fragments.
// R7: fixes R6's load-side swizzle constant (row bit 2 must map to addr bit 5:
// sw = (lane&6)<<3). 3-stage cp.async pipeline, one __syncthreads per k-iter,
// SW64 XOR swizzle, 96KB smem, 2 CTAs/SM.

#define KDIM 4096
#define NDIM 4096
#define MDIM 2048

// ---- device scratch (no runtime allocation allowed) ----
__device__ float         g_M01[16 * 16 * 16 * 16 * 16];      // 4 MB
__device__ __nv_bfloat16 g_xhi[(size_t)MDIM * KDIM];          // 16 MB
__device__ __nv_bfloat16 g_xlo[(size_t)MDIM * KDIM];          // 16 MB
__device__ __nv_bfloat16 g_wthi[(size_t)NDIM * KDIM];         // 32 MB  [o][in]
__device__ __nv_bfloat16 g_wtlo[(size_t)NDIM * KDIM];         // 32 MB  [o][in]

// ---------------------------------------------------------------------------
// helpers
// ---------------------------------------------------------------------------
__device__ __forceinline__ uint32_t smem_u32(const void* p) {
    uint32_t a;
    asm("{ .reg .u64 t; cvta.to.shared.u64 t, %1; cvt.u32.u64 %0, t; }"
        : "=r"(a) : "l"(p));
    return a;
}

__device__ __forceinline__ void cp16(uint32_t saddr, const void* gaddr) {
    asm volatile("cp.async.cg.shared.global [%0], [%1], 16;\n"
                 :: "r"(saddr), "l"(gaddr));
}
__device__ __forceinline__ void cp_commit() {
    asm volatile("cp.async.commit_group;\n" ::: "memory");
}

__device__ __forceinline__ void ldm4(uint32_t& r0, uint32_t& r1,
                                     uint32_t& r2, uint32_t& r3,
                                     uint32_t addr) {
    asm volatile("ldmatrix.sync.aligned.m8n8.x4.shared.b16 {%0,%1,%2,%3}, [%4];"
                 : "=r"(r0), "=r"(r1), "=r"(r2), "=r"(r3) : "r"(addr));
}

__device__ __forceinline__ void mma16816(float* c, const uint32_t* a,
                                         const uint32_t* b) {
    asm volatile(
        "mma.sync.aligned.m16n8k16.row.col.f32.bf16.bf16.f32 "
        "{%0,%1,%2,%3}, {%4,%5,%6,%7}, {%8,%9}, {%0,%1,%2,%3};"
        : "+f"(c[0]), "+f"(c[1]), "+f"(c[2]), "+f"(c[3])
        : "r"(a[0]), "r"(a[1]), "r"(a[2]), "r"(a[3]), "r"(b[0]), "r"(b[1]));
}

// ---------------------------------------------------------------------------
// x -> bf16 hi/lo split
// ---------------------------------------------------------------------------
__global__ __launch_bounds__(256) void cvt_x(const float* __restrict__ x) {
    const size_t base = ((size_t)blockIdx.x * 256 + threadIdx.x) * 8;
    float4 v0 = *(const float4*)(x + base);
    float4 v1 = *(const float4*)(x + base + 4);
    float f[8] = {v0.x, v0.y, v0.z, v0.w, v1.x, v1.y, v1.z, v1.w};
    __nv_bfloat16 hi[8], lo[8];
#pragma unroll
    for (int i = 0; i < 8; ++i) {
        hi[i] = __float2bfloat16(f[i]);
        lo[i] = __float2bfloat16(f[i] - __bfloat162float(hi[i]));
    }
    *(uint4*)(g_xhi + base) = *(uint4*)hi;
    *(uint4*)(g_xlo + base) = *(uint4*)lo;
}

// ---------------------------------------------------------------------------
// Stage 1: M01[i1,o1,i2,o2,r] = sum_q core0[i1,o1,q] * core1[q,i2,o2,r]
// ---------------------------------------------------------------------------
__global__ void tt_stage1(const float* __restrict__ core0,
                          const float* __restrict__ core1) {
    __shared__ float s_c0[4096];
    const int tid = threadIdx.x;
#pragma unroll
    for (int i = 0; i < 16; ++i) s_c0[tid + i * 256] = core0[tid + i * 256];
    __syncthreads();

    const int e  = blockIdx.x * 256 + tid;
    const int r  = e & 15;
    const int o2 = (e >> 4) & 15;
    const int i2 = (e >> 8) & 15;
    const int o1 = (e >> 12) & 15;
    const int i1 = (e >> 16) & 15;

    const float* c0p = s_c0 + i1 * 256 + o1 * 16;
    const float* c1p = core1 + i2 * 256 + o2 * 16 + r;
    float acc = 0.f;
#pragma unroll
    for (int q = 0; q < 16; ++q)
        acc = fmaf(c0p[q], c1p[q * 4096], acc);
    g_M01[e] = acc;
}

// ---------------------------------------------------------------------------
// Stage 2 (transposed output): Wt[o][in] as bf16 hi/lo split.
// ---------------------------------------------------------------------------
__global__ __launch_bounds__(256) void tt_stage2t(const float* __restrict__ core2) {
    __shared__ float s_c2t[4096];  // [r][o3][i3]
    const int tid = threadIdx.x;
#pragma unroll
    for (int i = 0; i < 16; ++i) {
        const int idx = tid + i * 256;          // src = r*256 + i3*16 + o3
        const int r = idx >> 8, i3 = (idx >> 4) & 15, o3 = idx & 15;
        s_c2t[r * 256 + o3 * 16 + i3] = core2[idx];
    }
    __syncthreads();

    const unsigned g = blockIdx.x * 256u + tid;   // 0 .. 2^20-1
    const int in  = g & 4095;
    const int ohi = g >> 12;                      // o1*16 + o2
    const int o1 = ohi >> 4, o2 = ohi & 15;
    const int i1 = in >> 8, i2 = (in >> 4) & 15, i3 = in & 15;

    const float* m = g_M01 + ((((i1 * 16 + o1) * 16 + i2) * 16 + o2) << 4);
    float m01[16];
#pragma unroll
    for (int r4 = 0; r4 < 4; ++r4) {
        float4 v = ((const float4*)m)[r4];
        m01[r4 * 4 + 0] = v.x; m01[r4 * 4 + 1] = v.y;
        m01[r4 * 4 + 2] = v.z; m01[r4 * 4 + 3] = v.w;
    }

#pragma unroll
    for (int o3 = 0; o3 < 16; ++o3) {
        float acc = 0.f;
#pragma unroll
        for (int r = 0; r < 16; ++r)
            acc = fmaf(m01[r], s_c2t[r * 256 + o3 * 16 + i3], acc);
        const __nv_bfloat16 h = __float2bfloat16(acc);
        const __nv_bfloat16 l = __float2bfloat16(acc - __bfloat162float(h));
        const size_t off = (size_t)(ohi * 16 + o3) * KDIM + in;
        g_wthi[off] = h;
        g_wtlo[off] = l;
    }
}

// ---------------------------------------------------------------------------
// GEMM: out[2048,4096] = x @ W + bias via mma.sync bf16x3
// CTA 128x128, BK=32, 8 warps (2x4), warp tile 64x32, 2 CTAs/SM.
// 64B rows with SW64 swizzle (off ^ ((off>>3)&0x30)); 3-stage pipeline,
// one __syncthreads per iteration.
// ---------------------------------------------------------------------------
#define TILE_BYTES  8192               // 128 rows x 64B
#define STAGE_BYTES (4 * TILE_BYTES)   // 32768 (Ahi, Alo, Bhi, Blo)
#define NSTAGE      3
#define SMEM_TOTAL  (NSTAGE * STAGE_BYTES)  // 98304

__device__ __forceinline__ void load_chunk(uint32_t sb, int stage, int c,
                                           int bm, int bn, int tid) {
    const __nv_bfloat16* bases[4] = {
        g_xhi  + ((size_t)bm * 128) * KDIM + (size_t)c * 32,
        g_xlo  + ((size_t)bm * 128) * KDIM + (size_t)c * 32,
        g_wthi + ((size_t)bn * 128) * KDIM + (size_t)c * 32,
        g_wtlo + ((size_t)bn * 128) * KDIM + (size_t)c * 32,
    };
#pragma unroll
    for (int t = 0; t < 4; ++t) {
        const uint32_t ts = sb + stage * STAGE_BYTES + t * TILE_BYTES;
        const char* gb = (const char*)bases[t];
#pragma unroll
        for (int i = 0; i < 2; ++i) {
            const int e   = tid + i * 256;   // 0..511
            const int row = e >> 2;          // 0..127
            const int seg = e & 3;           // 16B segment
            const uint32_t off = row * 64 + seg * 16;
            const uint32_t sw  = off ^ ((off >> 3) & 0x30);
            cp16(ts + sw, gb + (size_t)row * (KDIM * 2) + seg * 16);
        }
    }
    cp_commit();
}

__global__ void __launch_bounds__(256, 2)
tt_gemm_mma(const float* __restrict__ bias, float* __restrict__ out) {
    extern __shared__ __align__(128) char smem[];
    const uint32_t sb = smem_u32(smem);
    const int tid = threadIdx.x;
    const int lane = tid & 31;
    const int wid = tid >> 5;
    const int warpM = wid >> 2;      // 0..1
    const int warpN = wid & 3;       // 0..3
    const int bn = blockIdx.x, bm = blockIdx.y;

    float acc[4][4][4];
#pragma unroll
    for (int i = 0; i < 4; ++i)
#pragma unroll
        for (int j = 0; j < 4; ++j)
#pragma unroll
            for (int k = 0; k < 4; ++k) acc[i][j][k] = 0.f;

    // Store swizzle XORs addr bits 4-5 with row bits 1-2. Row bits 1-2 come
    // from lane bits 1-2 for both A and B lane->row maps (all other row terms
    // are multiples of 8). So: sw = ((lane & 6) << 3)  [bit1->bit4, bit2->bit5]
    const uint32_t sw = (uint32_t)((lane & 6) << 3);
    // A: row = warpM*64 + (lane&15) (+ mt*16); col16 = (lane>>4)*16 (+ ks*32)
    const uint32_t aRowOff = (uint32_t)(warpM * 64 + (lane & 15)) * 64;
    const uint32_t aColB   = (uint32_t)((lane >> 4) << 4);
    // B: row = warpN*32 + (lane&7) + ((lane>>4)&1)*8 (+ np*16); col16 = ((lane>>3)&1)*16
    const uint32_t bRowOff =
        (uint32_t)(warpN * 32 + (lane & 7) + ((lane >> 4) & 1) * 8) * 64;
    const uint32_t bColB = (uint32_t)(((lane >> 3) & 1) << 4);

    load_chunk(sb, 0, 0, bm, bn, tid);
    load_chunk(sb, 1, 1, bm, bn, tid);

    const int KT = KDIM / 32;  // 128
    int st = 0;
    for (int c = 0; c < KT; ++c) {
        if (c < KT - 1) asm volatile("cp.async.wait_group 1;" ::: "memory");
        else            asm volatile("cp.async.wait_group 0;" ::: "memory");
        __syncthreads();

        if (c + 2 < KT) {
            int st2 = st + 2; if (st2 >= NSTAGE) st2 -= NSTAGE;
            load_chunk(sb, st2, c + 2, bm, bn, tid);
        }

        const uint32_t sA  = sb + st * STAGE_BYTES;
        const uint32_t sAl = sA + TILE_BYTES;
        const uint32_t sB  = sA + 2 * TILE_BYTES;
        const uint32_t sBl = sA + 3 * TILE_BYTES;

#pragma unroll
        for (int ks = 0; ks < 2; ++ks) {
            const uint32_t aco = (aColB + ks * 32) ^ sw;
            const uint32_t bco = (bColB + ks * 32) ^ sw;

            // B fragments for this k-step: 16 regs
            uint32_t bh[4][2], bl[4][2];
#pragma unroll
            for (int np = 0; np < 2; ++np) {
                const uint32_t no = bRowOff + np * 16 * 64 + bco;
                uint32_t r0, r1, r2, r3;
                ldm4(r0, r1, r2, r3, sB + no);
                bh[np * 2][0] = r0; bh[np * 2][1] = r1;
                bh[np * 2 + 1][0] = r2; bh[np * 2 + 1][1] = r3;
                ldm4(r0, r1, r2, r3, sBl + no);
                bl[np * 2][0] = r0; bl[np * 2][1] = r1;
                bl[np * 2 + 1][0] = r2; bl[np * 2 + 1][1] = r3;
            }

            // Stream A fragments per mt
#pragma unroll
            for (int mt = 0; mt < 4; ++mt) {
                const uint32_t mo = aRowOff + mt * 16 * 64 + aco;
                uint32_t ah[4], al[4];
                ldm4(ah[0], ah[1], ah[2], ah[3], sA  + mo);
                ldm4(al[0], al[1], al[2], al[3], sAl + mo);
#pragma unroll
                for (int nt = 0; nt < 4; ++nt) {
                    mma16816(acc[mt][nt], ah, bh[nt]);
                    mma16816(acc[mt][nt], ah, bl[nt]);
                    mma16816(acc[mt][nt], al, bh[nt]);
                }
            }
        }

        st = (st + 1 == NSTAGE) ? 0 : st + 1;
    }

    // Epilogue: c-frag layout m16n8: lane -> rows l/4, l/4+8; cols 2*(l%4)
    const int rbase = bm * 128 + warpM * 64 + (lane >> 2);
    const int cbase = bn * 128 + warpN * 32 + (lane & 3) * 2;
#pragma unroll
    for (int nt = 0; nt < 4; ++nt) {
        const int col = cbase + nt * 8;
        const float b0 = bias[col], b1 = bias[col + 1];
#pragma unroll
        for (int mt = 0; mt < 4; ++mt) {
            const int row = rbase + mt * 16;
            float2 v0 = make_float2(acc[mt][nt][0] + b0, acc[mt][nt][1] + b1);
            float2 v1 = make_float2(acc[mt][nt][2] + b0, acc[mt][nt][3] + b1);
            *(float2*)(out + (size_t)row * NDIM + col) = v0;
            *(float2*)(out + (size_t)(row + 8) * NDIM + col) = v1;
        }
    }
}

// ---------------------------------------------------------------------------
extern "C" void kernel_launch(void* const* d_in, const int* in_sizes, int n_in,
                              void* d_out, int out_size) {
    const float* x     = (const float*)d_in[0];
    const float* core0 = (const float*)d_in[1];
    const float* core1 = (const float*)d_in[2];
    const float* core2 = (const float*)d_in[3];
    const float* bias  = (const float*)d_in[4];
    float* out = (float*)d_out;

    cudaFuncSetAttribute(tt_gemm_mma,
                         cudaFuncAttributeMaxDynamicSharedMemorySize,
                         SMEM_TOTAL);

    const int M = in_sizes[0] / KDIM;  // 2048

    cvt_x<<<(M * KDIM) / (256 * 8), 256>>>(x);
    tt_stage1<<<4096, 256>>>(core0, core1);
    tt_stage2t<<<4096, 256>>>(core2);

    dim3 grid(NDIM / 128, M / 128);  // (32, 16)
    tt_gemm_mma<<<grid, 256, SMEM_TOTAL>>>(bias, out);
}

// round 8
// speedup vs baseline: 4.0498x; 1.3442x over previous
#include <cuda_runtime.h>
#include <cuda_fp16.h>
#include <cstdint>

// TensorTrainLinear: out = x @ W + bias.
// W (4096x4096) materialized from TT cores each launch, stored fp16.
// x split into fp16 hi/lo (Dekker); GEMM = mma.sync m16n8k16 f16 with TWO
// products (xh*W + xl*W) in fp32 fragments. Dropped term (W - fp16(W))*x
// gives rel_err ~3e-4 << 1e-3 threshold.
// R8: 2-product fp16 (tensor work x2/3 vs bf16x3), 4-stage cp.async pipeline
// (24KB/stage), 2 CTAs/SM.

#define KDIM 4096
#define NDIM 4096
#define MDIM 2048

// ---- device scratch (no runtime allocation allowed) ----
__device__ float  g_M01[16 * 16 * 16 * 16 * 16];        // 4 MB
__device__ __half g_xhi[(size_t)MDIM * KDIM];            // 16 MB
__device__ __half g_xlo[(size_t)MDIM * KDIM];            // 16 MB
__device__ __half g_wt[(size_t)NDIM * KDIM];             // 32 MB  [o][in]

// ---------------------------------------------------------------------------
// helpers
// ---------------------------------------------------------------------------
__device__ __forceinline__ uint32_t smem_u32(const void* p) {
    uint32_t a;
    asm("{ .reg .u64 t; cvta.to.shared.u64 t, %1; cvt.u32.u64 %0, t; }"
        : "=r"(a) : "l"(p));
    return a;
}

__device__ __forceinline__ void cp16(uint32_t saddr, const void* gaddr) {
    asm volatile("cp.async.cg.shared.global [%0], [%1], 16;\n"
                 :: "r"(saddr), "l"(gaddr));
}
__device__ __forceinline__ void cp_commit() {
    asm volatile("cp.async.commit_group;\n" ::: "memory");
}

__device__ __forceinline__ void ldm4(uint32_t& r0, uint32_t& r1,
                                     uint32_t& r2, uint32_t& r3,
                                     uint32_t addr) {
    asm volatile("ldmatrix.sync.aligned.m8n8.x4.shared.b16 {%0,%1,%2,%3}, [%4];"
                 : "=r"(r0), "=r"(r1), "=r"(r2), "=r"(r3) : "r"(addr));
}

__device__ __forceinline__ void mma16816(float* c, const uint32_t* a,
                                         const uint32_t* b) {
    asm volatile(
        "mma.sync.aligned.m16n8k16.row.col.f32.f16.f16.f32 "
        "{%0,%1,%2,%3}, {%4,%5,%6,%7}, {%8,%9}, {%0,%1,%2,%3};"
        : "+f"(c[0]), "+f"(c[1]), "+f"(c[2]), "+f"(c[3])
        : "r"(a[0]), "r"(a[1]), "r"(a[2]), "r"(a[3]), "r"(b[0]), "r"(b[1]));
}

// ---------------------------------------------------------------------------
// x -> fp16 hi/lo split (Dekker residual; both normal-range)
// ---------------------------------------------------------------------------
__global__ __launch_bounds__(256) void cvt_x(const float* __restrict__ x) {
    const size_t base = ((size_t)blockIdx.x * 256 + threadIdx.x) * 8;
    float4 v0 = *(const float4*)(x + base);
    float4 v1 = *(const float4*)(x + base + 4);
    float f[8] = {v0.x, v0.y, v0.z, v0.w, v1.x, v1.y, v1.z, v1.w};
    __half hi[8], lo[8];
#pragma unroll
    for (int i = 0; i < 8; ++i) {
        hi[i] = __float2half(f[i]);
        lo[i] = __float2half(f[i] - __half2float(hi[i]));
    }
    *(uint4*)(g_xhi + base) = *(uint4*)hi;
    *(uint4*)(g_xlo + base) = *(uint4*)lo;
}

// ---------------------------------------------------------------------------
// Stage 1: M01[i1,o1,i2,o2,r] = sum_q core0[i1,o1,q] * core1[q,i2,o2,r]
// ---------------------------------------------------------------------------
__global__ void tt_stage1(const float* __restrict__ core0,
                          const float* __restrict__ core1) {
    __shared__ float s_c0[4096];
    const int tid = threadIdx.x;
#pragma unroll
    for (int i = 0; i < 16; ++i) s_c0[tid + i * 256] = core0[tid + i * 256];
    __syncthreads();

    const int e  = blockIdx.x * 256 + tid;
    const int r  = e & 15;
    const int o2 = (e >> 4) & 15;
    const int i2 = (e >> 8) & 15;
    const int o1 = (e >> 12) & 15;
    const int i1 = (e >> 16) & 15;

    const float* c0p = s_c0 + i1 * 256 + o1 * 16;
    const float* c1p = core1 + i2 * 256 + o2 * 16 + r;
    float acc = 0.f;
#pragma unroll
    for (int q = 0; q < 16; ++q)
        acc = fmaf(c0p[q], c1p[q * 4096], acc);
    g_M01[e] = acc;
}

// ---------------------------------------------------------------------------
// Stage 2 (transposed output): Wt[o][in] as fp16.
// ---------------------------------------------------------------------------
__global__ __launch_bounds__(256) void tt_stage2t(const float* __restrict__ core2) {
    __shared__ float s_c2t[4096];  // [r][o3][i3]
    const int tid = threadIdx.x;
#pragma unroll
    for (int i = 0; i < 16; ++i) {
        const int idx = tid + i * 256;          // src = r*256 + i3*16 + o3
        const int r = idx >> 8, i3 = (idx >> 4) & 15, o3 = idx & 15;
        s_c2t[r * 256 + o3 * 16 + i3] = core2[idx];
    }
    __syncthreads();

    const unsigned g = blockIdx.x * 256u + tid;   // 0 .. 2^20-1
    const int in  = g & 4095;
    const int ohi = g >> 12;                      // o1*16 + o2
    const int o1 = ohi >> 4, o2 = ohi & 15;
    const int i1 = in >> 8, i2 = (in >> 4) & 15, i3 = in & 15;

    const float* m = g_M01 + ((((i1 * 16 + o1) * 16 + i2) * 16 + o2) << 4);
    float m01[16];
#pragma unroll
    for (int r4 = 0; r4 < 4; ++r4) {
        float4 v = ((const float4*)m)[r4];
        m01[r4 * 4 + 0] = v.x; m01[r4 * 4 + 1] = v.y;
        m01[r4 * 4 + 2] = v.z; m01[r4 * 4 + 3] = v.w;
    }

#pragma unroll
    for (int o3 = 0; o3 < 16; ++o3) {
        float acc = 0.f;
#pragma unroll
        for (int r = 0; r < 16; ++r)
            acc = fmaf(m01[r], s_c2t[r * 256 + o3 * 16 + i3], acc);
        g_wt[(size_t)(ohi * 16 + o3) * KDIM + in] = __float2half(acc);
    }
}

// ---------------------------------------------------------------------------
// GEMM: out[2048,4096] = x @ W + bias via mma.sync fp16 x2
// CTA 128x128, BK=32, 8 warps (2x4), warp tile 64x32, 2 CTAs/SM.
// 64B rows with SW64 swizzle (off ^ ((off>>3)&0x30)); 4-stage pipeline,
// prefetch distance 3, one __syncthreads per iteration.
// ---------------------------------------------------------------------------
#define TILE_BYTES  8192               // 128 rows x 64B
#define STAGE_BYTES (3 * TILE_BYTES)   // 24576 (Ahi, Alo, B)
#define NSTAGE      4
#define SMEM_TOTAL  (NSTAGE * STAGE_BYTES)  // 98304

__device__ __forceinline__ void load_chunk(uint32_t sb, int stage, int c,
                                           int bm, int bn, int tid) {
    const __half* bases[3] = {
        g_xhi + ((size_t)bm * 128) * KDIM + (size_t)c * 32,
        g_xlo + ((size_t)bm * 128) * KDIM + (size_t)c * 32,
        g_wt  + ((size_t)bn * 128) * KDIM + (size_t)c * 32,
    };
#pragma unroll
    for (int t = 0; t < 3; ++t) {
        const uint32_t ts = sb + stage * STAGE_BYTES + t * TILE_BYTES;
        const char* gb = (const char*)bases[t];
#pragma unroll
        for (int i = 0; i < 2; ++i) {
            const int e   = tid + i * 256;   // 0..511
            const int row = e >> 2;          // 0..127
            const int seg = e & 3;           // 16B segment
            const uint32_t off = row * 64 + seg * 16;
            const uint32_t sw  = off ^ ((off >> 3) & 0x30);
            cp16(ts + sw, gb + (size_t)row * (KDIM * 2) + seg * 16);
        }
    }
    cp_commit();
}

__global__ void __launch_bounds__(256, 2)
tt_gemm_mma(const float* __restrict__ bias, float* __restrict__ out) {
    extern __shared__ __align__(128) char smem[];
    const uint32_t sb = smem_u32(smem);
    const int tid = threadIdx.x;
    const int lane = tid & 31;
    const int wid = tid >> 5;
    const int warpM = wid >> 2;      // 0..1
    const int warpN = wid & 3;       // 0..3
    const int bn = blockIdx.x, bm = blockIdx.y;

    float acc[4][4][4];
#pragma unroll
    for (int i = 0; i < 4; ++i)
#pragma unroll
        for (int j = 0; j < 4; ++j)
#pragma unroll
            for (int k = 0; k < 4; ++k) acc[i][j][k] = 0.f;

    // Store swizzle XORs addr bits 4-5 with row bits 1-2 -> load side:
    // sw = (lane & 6) << 3  (bit1->bit4, bit2->bit5)
    const uint32_t sw = (uint32_t)((lane & 6) << 3);
    // A: row = warpM*64 + (lane&15) (+ mt*16); col16 = (lane>>4)*16 (+ ks*32)
    const uint32_t aRowOff = (uint32_t)(warpM * 64 + (lane & 15)) * 64;
    const uint32_t aColB   = (uint32_t)((lane >> 4) << 4);
    // B: row = warpN*32 + (lane&7) + ((lane>>4)&1)*8 (+ np*16); col16 = ((lane>>3)&1)*16
    const uint32_t bRowOff =
        (uint32_t)(warpN * 32 + (lane & 7) + ((lane >> 4) & 1) * 8) * 64;
    const uint32_t bColB = (uint32_t)(((lane >> 3) & 1) << 4);

    load_chunk(sb, 0, 0, bm, bn, tid);
    load_chunk(sb, 1, 1, bm, bn, tid);
    load_chunk(sb, 2, 2, bm, bn, tid);

    const int KT = KDIM / 32;  // 128
    int st = 0;
    for (int c = 0; c < KT; ++c) {
        // Ensure chunk c landed: pending groups = {c .. min(c+2, KT-1)}
        if (c + 2 < KT)      asm volatile("cp.async.wait_group 2;" ::: "memory");
        else if (c + 1 < KT) asm volatile("cp.async.wait_group 1;" ::: "memory");
        else                 asm volatile("cp.async.wait_group 0;" ::: "memory");
        __syncthreads();

        if (c + 3 < KT) {
            int st3 = st + 3; if (st3 >= NSTAGE) st3 -= NSTAGE;
            load_chunk(sb, st3, c + 3, bm, bn, tid);
        }

        const uint32_t sA  = sb + st * STAGE_BYTES;
        const uint32_t sAl = sA + TILE_BYTES;
        const uint32_t sB  = sA + 2 * TILE_BYTES;

#pragma unroll
        for (int ks = 0; ks < 2; ++ks) {
            const uint32_t aco = (aColB + ks * 32) ^ sw;
            const uint32_t bco = (bColB + ks * 32) ^ sw;

            // B fragments for this k-step: 8 regs
            uint32_t bw[4][2];
#pragma unroll
            for (int np = 0; np < 2; ++np) {
                const uint32_t no = bRowOff + np * 16 * 64 + bco;
                uint32_t r0, r1, r2, r3;
                ldm4(r0, r1, r2, r3, sB + no);
                bw[np * 2][0] = r0; bw[np * 2][1] = r1;
                bw[np * 2 + 1][0] = r2; bw[np * 2 + 1][1] = r3;
            }

            // Stream A fragments per mt
#pragma unroll
            for (int mt = 0; mt < 4; ++mt) {
                const uint32_t mo = aRowOff + mt * 16 * 64 + aco;
                uint32_t ah[4], al[4];
                ldm4(ah[0], ah[1], ah[2], ah[3], sA  + mo);
                ldm4(al[0], al[1], al[2], al[3], sAl + mo);
#pragma unroll
                for (int nt = 0; nt < 4; ++nt) {
                    mma16816(acc[mt][nt], ah, bw[nt]);
                    mma16816(acc[mt][nt], al, bw[nt]);
                }
            }
        }

        st = (st + 1 == NSTAGE) ? 0 : st + 1;
    }

    // Epilogue: c-frag layout m16n8: lane -> rows l/4, l/4+8; cols 2*(l%4)
    const int rbase = bm * 128 + warpM * 64 + (lane >> 2);
    const int cbase = bn * 128 + warpN * 32 + (lane & 3) * 2;
#pragma unroll
    for (int nt = 0; nt < 4; ++nt) {
        const int col = cbase + nt * 8;
        const float b0 = bias[col], b1 = bias[col + 1];
#pragma unroll
        for (int mt = 0; mt < 4; ++mt) {
            const int row = rbase + mt * 16;
            float2 v0 = make_float2(acc[mt][nt][0] + b0, acc[mt][nt][1] + b1);
            float2 v1 = make_float2(acc[mt][nt][2] + b0, acc[mt][nt][3] + b1);
            *(float2*)(out + (size_t)row * NDIM + col) = v0;
            *(float2*)(out + (size_t)(row + 8) * NDIM + col) = v1;
        }
    }
}

// ---------------------------------------------------------------------------
extern "C" void kernel_launch(void* const* d_in, const int* in_sizes, int n_in,
                              void* d_out, int out_size) {
    const float* x     = (const float*)d_in[0];
    const float* core0 = (const float*)d_in[1];
    const float* core1 = (const float*)d_in[2];
    const float* core2 = (const float*)d_in[3];
    const float* bias  = (const float*)d_in[4];
    float* out = (float*)d_out;

    cudaFuncSetAttribute(tt_gemm_mma,
                         cudaFuncAttributeMaxDynamicSharedMemorySize,
                         SMEM_TOTAL);

    const int M = in_sizes[0] / KDIM;  // 2048

    cvt_x<<<(M * KDIM) / (256 * 8), 256>>>(x);
    tt_stage1<<<4096, 256>>>(core0, core1);
    tt_stage2t<<<4096, 256>>>(core2);

    dim3 grid(NDIM / 128, M / 128);  // (32, 16)
    tt_gemm_mma<<<grid, 256, SMEM_TOTAL>>>(bias, out);
}

// round 9
// speedup vs baseline: 4.1182x; 1.0169x over previous
#include <cuda_runtime.h>
#include <cuda_fp16.h>
#include <cstdint>

// TensorTrainLinear: out = x @ W + bias.
// W (4096x4096) materialized from TT cores each launch, stored fp16 [o][in].
// x split into fp16 hi/lo (Dekker); GEMM = mma.sync m16n8k16 f16 with TWO
// products (xh*W + xl*W) in fp32 fragments (rel_err ~2e-4 << 1e-3).
// R9: (1) single fused prep kernel: blocks 0-4095 convert x, blocks 4096-8191
//     build W with the core0*core1 contraction done per-block in smem (no
//     M01 global round-trip, one launch instead of three).
//     (2) GEMM inner loop reordered: all hi-MMAs then all lo-MMAs per mt,
//     breaking the acc RAW chain between split products (dist 1 -> 4).

#define KDIM 4096
#define NDIM 4096
#define MDIM 2048

// ---- device scratch (no runtime allocation allowed) ----
__device__ __half g_xhi[(size_t)MDIM * KDIM];            // 16 MB
__device__ __half g_xlo[(size_t)MDIM * KDIM];            // 16 MB
__device__ __half g_wt[(size_t)NDIM * KDIM];             // 32 MB  [o][in]

// ---------------------------------------------------------------------------
// helpers
// ---------------------------------------------------------------------------
__device__ __forceinline__ uint32_t smem_u32(const void* p) {
    uint32_t a;
    asm("{ .reg .u64 t; cvta.to.shared.u64 t, %1; cvt.u32.u64 %0, t; }"
        : "=r"(a) : "l"(p));
    return a;
}

__device__ __forceinline__ void cp16(uint32_t saddr, const void* gaddr) {
    asm volatile("cp.async.cg.shared.global [%0], [%1], 16;\n"
                 :: "r"(saddr), "l"(gaddr));
}
__device__ __forceinline__ void cp_commit() {
    asm volatile("cp.async.commit_group;\n" ::: "memory");
}

__device__ __forceinline__ void ldm4(uint32_t& r0, uint32_t& r1,
                                     uint32_t& r2, uint32_t& r3,
                                     uint32_t addr) {
    asm volatile("ldmatrix.sync.aligned.m8n8.x4.shared.b16 {%0,%1,%2,%3}, [%4];"
                 : "=r"(r0), "=r"(r1), "=r"(r2), "=r"(r3) : "r"(addr));
}

__device__ __forceinline__ void mma16816(float* c, const uint32_t* a,
                                         const uint32_t* b) {
    asm volatile(
        "mma.sync.aligned.m16n8k16.row.col.f32.f16.f16.f32 "
        "{%0,%1,%2,%3}, {%4,%5,%6,%7}, {%8,%9}, {%0,%1,%2,%3};"
        : "+f"(c[0]), "+f"(c[1]), "+f"(c[2]), "+f"(c[3])
        : "r"(a[0]), "r"(a[1]), "r"(a[2]), "r"(a[3]), "r"(b[0]), "r"(b[1]));
}

// ---------------------------------------------------------------------------
// Fused prep: blocks [0,4096): x -> fp16 hi/lo split.
//             blocks [4096,8192): W build. Block b' = b-4096 owns fixed
//             (o1,o2,i1); threads give (i2,i3); o3 looped.
//   M01 slice [i2][r] = sum_q core0[i1,o1,q] * core1[q,i2,o2,r]  (in smem)
//   Wt[o][in]         = sum_r M01[i2][r] * core2[r,i3,o3]
// ---------------------------------------------------------------------------
__global__ __launch_bounds__(256) void tt_prep(const float* __restrict__ x,
                                               const float* __restrict__ core0,
                                               const float* __restrict__ core1,
                                               const float* __restrict__ core2) {
    const int tid = threadIdx.x;

    if (blockIdx.x < 4096) {
        // ---- x conversion ----
        const size_t base = ((size_t)blockIdx.x * 256 + tid) * 8;
        float4 v0 = *(const float4*)(x + base);
        float4 v1 = *(const float4*)(x + base + 4);
        float f[8] = {v0.x, v0.y, v0.z, v0.w, v1.x, v1.y, v1.z, v1.w};
        __half hi[8], lo[8];
#pragma unroll
        for (int i = 0; i < 8; ++i) {
            hi[i] = __float2half(f[i]);
            lo[i] = __float2half(f[i] - __half2float(hi[i]));
        }
        *(uint4*)(g_xhi + base) = *(uint4*)hi;
        *(uint4*)(g_xlo + base) = *(uint4*)lo;
        return;
    }

    // ---- W build ----
    __shared__ float s_c2t[4096];   // [r][o3][i3]
    __shared__ float s_m01[256];    // [i2][r]
    __shared__ float s_c0[16];

    const int b   = blockIdx.x - 4096;     // 0..4095
    const int ohi = b >> 4;                // o1*16 + o2
    const int o2  = ohi & 15;
    const int i1  = b & 15;

    // core2 transposed into smem: src = r*256 + i3*16 + o3 -> [r][o3][i3]
#pragma unroll
    for (int i = 0; i < 16; ++i) {
        const int idx = tid + i * 256;
        const int r = idx >> 8, i3s = (idx >> 4) & 15, o3s = idx & 15;
        s_c2t[r * 256 + o3s * 16 + i3s] = core2[idx];
    }
    if (tid < 16) s_c0[tid] = core0[i1 * 256 + (ohi >> 4) * 16 + tid];
    __syncthreads();

    // M01 slice: thread tid = i2*16 + r
    {
        const int i2s = tid >> 4, r = tid & 15;
        const float* c1p = core1 + i2s * 256 + o2 * 16 + r;
        float acc = 0.f;
#pragma unroll
        for (int q = 0; q < 16; ++q)
            acc = fmaf(s_c0[q], c1p[q * 4096], acc);
        s_m01[tid] = acc;
    }
    __syncthreads();

    const int i2 = tid >> 4, i3 = tid & 15;
    const int in = i1 * 256 + i2 * 16 + i3;
    float m01[16];
#pragma unroll
    for (int r = 0; r < 16; ++r) m01[r] = s_m01[i2 * 16 + r];

#pragma unroll
    for (int o3 = 0; o3 < 16; ++o3) {
        float acc = 0.f;
#pragma unroll
        for (int r = 0; r < 16; ++r)
            acc = fmaf(m01[r], s_c2t[r * 256 + o3 * 16 + i3], acc);
        g_wt[(size_t)(ohi * 16 + o3) * KDIM + in] = __float2half(acc);
    }
}

// ---------------------------------------------------------------------------
// GEMM: out[2048,4096] = x @ W + bias via mma.sync fp16 x2
// CTA 128x128, BK=32, 8 warps (2x4), warp tile 64x32, 2 CTAs/SM.
// 64B rows with SW64 swizzle (off ^ ((off>>3)&0x30)); 4-stage pipeline,
// prefetch distance 3, one __syncthreads per iteration.
// ---------------------------------------------------------------------------
#define TILE_BYTES  8192               // 128 rows x 64B
#define STAGE_BYTES (3 * TILE_BYTES)   // 24576 (Ahi, Alo, B)
#define NSTAGE      4
#define SMEM_TOTAL  (NSTAGE * STAGE_BYTES)  // 98304

__device__ __forceinline__ void load_chunk(uint32_t sb, int stage, int c,
                                           int bm, int bn, int tid) {
    const __half* bases[3] = {
        g_xhi + ((size_t)bm * 128) * KDIM + (size_t)c * 32,
        g_xlo + ((size_t)bm * 128) * KDIM + (size_t)c * 32,
        g_wt  + ((size_t)bn * 128) * KDIM + (size_t)c * 32,
    };
#pragma unroll
    for (int t = 0; t < 3; ++t) {
        const uint32_t ts = sb + stage * STAGE_BYTES + t * TILE_BYTES;
        const char* gb = (const char*)bases[t];
#pragma unroll
        for (int i = 0; i < 2; ++i) {
            const int e   = tid + i * 256;   // 0..511
            const int row = e >> 2;          // 0..127
            const int seg = e & 3;           // 16B segment
            const uint32_t off = row * 64 + seg * 16;
            const uint32_t sw  = off ^ ((off >> 3) & 0x30);
            cp16(ts + sw, gb + (size_t)row * (KDIM * 2) + seg * 16);
        }
    }
    cp_commit();
}

__global__ void __launch_bounds__(256, 2)
tt_gemm_mma(const float* __restrict__ bias, float* __restrict__ out) {
    extern __shared__ __align__(128) char smem[];
    const uint32_t sb = smem_u32(smem);
    const int tid = threadIdx.x;
    const int lane = tid & 31;
    const int wid = tid >> 5;
    const int warpM = wid >> 2;      // 0..1
    const int warpN = wid & 3;       // 0..3
    const int bn = blockIdx.x, bm = blockIdx.y;

    float acc[4][4][4];
#pragma unroll
    for (int i = 0; i < 4; ++i)
#pragma unroll
        for (int j = 0; j < 4; ++j)
#pragma unroll
            for (int k = 0; k < 4; ++k) acc[i][j][k] = 0.f;

    // Load-side swizzle: sw = (lane & 6) << 3  (row bit1->addr bit4, bit2->bit5)
    const uint32_t sw = (uint32_t)((lane & 6) << 3);
    const uint32_t aRowOff = (uint32_t)(warpM * 64 + (lane & 15)) * 64;
    const uint32_t aColB   = (uint32_t)((lane >> 4) << 4);
    const uint32_t bRowOff =
        (uint32_t)(warpN * 32 + (lane & 7) + ((lane >> 4) & 1) * 8) * 64;
    const uint32_t bColB = (uint32_t)(((lane >> 3) & 1) << 4);

    load_chunk(sb, 0, 0, bm, bn, tid);
    load_chunk(sb, 1, 1, bm, bn, tid);
    load_chunk(sb, 2, 2, bm, bn, tid);

    const int KT = KDIM / 32;  // 128
    int st = 0;
    for (int c = 0; c < KT; ++c) {
        if (c + 2 < KT)      asm volatile("cp.async.wait_group 2;" ::: "memory");
        else if (c + 1 < KT) asm volatile("cp.async.wait_group 1;" ::: "memory");
        else                 asm volatile("cp.async.wait_group 0;" ::: "memory");
        __syncthreads();

        if (c + 3 < KT) {
            int st3 = st + 3; if (st3 >= NSTAGE) st3 -= NSTAGE;
            load_chunk(sb, st3, c + 3, bm, bn, tid);
        }

        const uint32_t sA  = sb + st * STAGE_BYTES;
        const uint32_t sAl = sA + TILE_BYTES;
        const uint32_t sB  = sA + 2 * TILE_BYTES;

#pragma unroll
        for (int ks = 0; ks < 2; ++ks) {
            const uint32_t aco = (aColB + ks * 32) ^ sw;
            const uint32_t bco = (bColB + ks * 32) ^ sw;

            // B fragments for this k-step: 8 regs
            uint32_t bw[4][2];
#pragma unroll
            for (int np = 0; np < 2; ++np) {
                const uint32_t no = bRowOff + np * 16 * 64 + bco;
                uint32_t r0, r1, r2, r3;
                ldm4(r0, r1, r2, r3, sB + no);
                bw[np * 2][0] = r0; bw[np * 2][1] = r1;
                bw[np * 2 + 1][0] = r2; bw[np * 2 + 1][1] = r3;
            }

            // Stream A fragments per mt; hi-sweep then lo-sweep so the two
            // writes to each acc[mt][nt] are 4 HMMAs apart (no RAW stall).
#pragma unroll
            for (int mt = 0; mt < 4; ++mt) {
                const uint32_t mo = aRowOff + mt * 16 * 64 + aco;
                uint32_t ah[4], al[4];
                ldm4(ah[0], ah[1], ah[2], ah[3], sA  + mo);
                ldm4(al[0], al[1], al[2], al[3], sAl + mo);
#pragma unroll
                for (int nt = 0; nt < 4; ++nt)
                    mma16816(acc[mt][nt], ah, bw[nt]);
#pragma unroll
                for (int nt = 0; nt < 4; ++nt)
                    mma16816(acc[mt][nt], al, bw[nt]);
            }
        }

        st = (st + 1 == NSTAGE) ? 0 : st + 1;
    }

    // Epilogue: c-frag layout m16n8: lane -> rows l/4, l/4+8; cols 2*(l%4)
    const int rbase = bm * 128 + warpM * 64 + (lane >> 2);
    const int cbase = bn * 128 + warpN * 32 + (lane & 3) * 2;
#pragma unroll
    for (int nt = 0; nt < 4; ++nt) {
        const int col = cbase + nt * 8;
        const float b0 = bias[col], b1 = bias[col + 1];
#pragma unroll
        for (int mt = 0; mt < 4; ++mt) {
            const int row = rbase + mt * 16;
            float2 v0 = make_float2(acc[mt][nt][0] + b0, acc[mt][nt][1] + b1);
            float2 v1 = make_float2(acc[mt][nt][2] + b0, acc[mt][nt][3] + b1);
            *(float2*)(out + (size_t)row * NDIM + col) = v0;
            *(float2*)(out + (size_t)(row + 8) * NDIM + col) = v1;
        }
    }
}

// ---------------------------------------------------------------------------
extern "C" void kernel_launch(void* const* d_in, const int* in_sizes, int n_in,
                              void* d_out, int out_size) {
    const float* x     = (const float*)d_in[0];
    const float* core0 = (const float*)d_in[1];
    const float* core1 = (const float*)d_in[2];
    const float* core2 = (const float*)d_in[3];
    const float* bias  = (const float*)d_in[4];
    float* out = (float*)d_out;

    cudaFuncSetAttribute(tt_gemm_mma,
                         cudaFuncAttributeMaxDynamicSharedMemorySize,
                         SMEM_TOTAL);

    tt_prep<<<8192, 256>>>(x, core0, core1, core2);

    dim3 grid(NDIM / 128, MDIM / 128);  // (32, 16)
    tt_gemm_mma<<<grid, 256, SMEM_TOTAL>>>(bias, out);
}

// round 10
// speedup vs baseline: 7.2874x; 1.7695x over previous
#include <cuda_runtime.h>
#include <cuda_fp16.h>
#include <cstdint>

// TensorTrainLinear: out = x @ W + bias.
// W (4096x4096) materialized from TT cores each launch, stored fp16 [o][in].
// R10: SINGLE-product fp16 GEMM: out = fp16(x) @ fp16(W) + bias, fp32
// accumulate. Dropped residuals (x-xh)*W and (W-W16)*x give predicted
// rel_err ~2.9e-4 (measured 2.07e-4 with only W residual dropped) < 1e-3.
// BK=64 (128B rows, SW128 swizzle), 3-stage cp.async pipeline, 64 iters
// (half the barriers of R9), 2 CTAs/SM.

#define KDIM 4096
#define NDIM 4096
#define MDIM 2048

// ---- device scratch (no runtime allocation allowed) ----
__device__ __half g_xh[(size_t)MDIM * KDIM];             // 16 MB
__device__ __half g_wt[(size_t)NDIM * KDIM];             // 32 MB  [o][in]

// ---------------------------------------------------------------------------
// helpers
// ---------------------------------------------------------------------------
__device__ __forceinline__ uint32_t smem_u32(const void* p) {
    uint32_t a;
    asm("{ .reg .u64 t; cvta.to.shared.u64 t, %1; cvt.u32.u64 %0, t; }"
        : "=r"(a) : "l"(p));
    return a;
}

__device__ __forceinline__ void cp16(uint32_t saddr, const void* gaddr) {
    asm volatile("cp.async.cg.shared.global [%0], [%1], 16;\n"
                 :: "r"(saddr), "l"(gaddr));
}
__device__ __forceinline__ void cp_commit() {
    asm volatile("cp.async.commit_group;\n" ::: "memory");
}

__device__ __forceinline__ void ldm4(uint32_t& r0, uint32_t& r1,
                                     uint32_t& r2, uint32_t& r3,
                                     uint32_t addr) {
    asm volatile("ldmatrix.sync.aligned.m8n8.x4.shared.b16 {%0,%1,%2,%3}, [%4];"
                 : "=r"(r0), "=r"(r1), "=r"(r2), "=r"(r3) : "r"(addr));
}

__device__ __forceinline__ void mma16816(float* c, const uint32_t* a,
                                         const uint32_t* b) {
    asm volatile(
        "mma.sync.aligned.m16n8k16.row.col.f32.f16.f16.f32 "
        "{%0,%1,%2,%3}, {%4,%5,%6,%7}, {%8,%9}, {%0,%1,%2,%3};"
        : "+f"(c[0]), "+f"(c[1]), "+f"(c[2]), "+f"(c[3])
        : "r"(a[0]), "r"(a[1]), "r"(a[2]), "r"(a[3]), "r"(b[0]), "r"(b[1]));
}

// ---------------------------------------------------------------------------
// Fused prep: blocks [0,4096): x -> fp16.
//             blocks [4096,8192): W build (core chain contraction in smem).
// ---------------------------------------------------------------------------
__global__ __launch_bounds__(256) void tt_prep(const float* __restrict__ x,
                                               const float* __restrict__ core0,
                                               const float* __restrict__ core1,
                                               const float* __restrict__ core2) {
    const int tid = threadIdx.x;

    if (blockIdx.x < 4096) {
        // ---- x conversion ----
        const size_t base = ((size_t)blockIdx.x * 256 + tid) * 8;
        float4 v0 = *(const float4*)(x + base);
        float4 v1 = *(const float4*)(x + base + 4);
        float f[8] = {v0.x, v0.y, v0.z, v0.w, v1.x, v1.y, v1.z, v1.w};
        __half h[8];
#pragma unroll
        for (int i = 0; i < 8; ++i) h[i] = __float2half(f[i]);
        *(uint4*)(g_xh + base) = *(uint4*)h;
        return;
    }

    // ---- W build ----
    __shared__ float s_c2t[4096];   // [r][o3][i3]
    __shared__ float s_m01[256];    // [i2][r]
    __shared__ float s_c0[16];

    const int b   = blockIdx.x - 4096;     // 0..4095
    const int ohi = b >> 4;                // o1*16 + o2
    const int o2  = ohi & 15;
    const int i1  = b & 15;

    // core2 transposed into smem: src = r*256 + i3*16 + o3 -> [r][o3][i3]
#pragma unroll
    for (int i = 0; i < 16; ++i) {
        const int idx = tid + i * 256;
        const int r = idx >> 8, i3s = (idx >> 4) & 15, o3s = idx & 15;
        s_c2t[r * 256 + o3s * 16 + i3s] = core2[idx];
    }
    if (tid < 16) s_c0[tid] = core0[i1 * 256 + (ohi >> 4) * 16 + tid];
    __syncthreads();

    // M01 slice: thread tid = i2*16 + r
    {
        const int i2s = tid >> 4, r = tid & 15;
        const float* c1p = core1 + i2s * 256 + o2 * 16 + r;
        float acc = 0.f;
#pragma unroll
        for (int q = 0; q < 16; ++q)
            acc = fmaf(s_c0[q], c1p[q * 4096], acc);
        s_m01[tid] = acc;
    }
    __syncthreads();

    const int i2 = tid >> 4, i3 = tid & 15;
    const int in = i1 * 256 + i2 * 16 + i3;
    float m01[16];
#pragma unroll
    for (int r = 0; r < 16; ++r) m01[r] = s_m01[i2 * 16 + r];

#pragma unroll
    for (int o3 = 0; o3 < 16; ++o3) {
        float acc = 0.f;
#pragma unroll
        for (int r = 0; r < 16; ++r)
            acc = fmaf(m01[r], s_c2t[r * 256 + o3 * 16 + i3], acc);
        g_wt[(size_t)(ohi * 16 + o3) * KDIM + in] = __float2half(acc);
    }
}

// ---------------------------------------------------------------------------
// GEMM: out[2048,4096] = xh @ W16 + bias via mma.sync fp16, single product.
// CTA 128x128, BK=64, 8 warps (2x4), warp tile 64x32, 2 CTAs/SM.
// 128B rows, SW128 swizzle (off ^ ((off>>3)&0x70)); 3-stage pipeline,
// one __syncthreads per iteration, 64 iterations.
// ---------------------------------------------------------------------------
#define TILE_BYTES  16384              // 128 rows x 128B
#define STAGE_BYTES (2 * TILE_BYTES)   // 32768 (A, B)
#define NSTAGE      3
#define SMEM_TOTAL  (NSTAGE * STAGE_BYTES)  // 98304

__device__ __forceinline__ void load_chunk(uint32_t sb, int stage, int c,
                                           int bm, int bn, int tid) {
    const __half* bases[2] = {
        g_xh + ((size_t)bm * 128) * KDIM + (size_t)c * 64,
        g_wt + ((size_t)bn * 128) * KDIM + (size_t)c * 64,
    };
#pragma unroll
    for (int t = 0; t < 2; ++t) {
        const uint32_t ts = sb + stage * STAGE_BYTES + t * TILE_BYTES;
        const char* gb = (const char*)bases[t];
#pragma unroll
        for (int i = 0; i < 4; ++i) {
            const int e   = tid + i * 256;   // 0..1023
            const int row = e >> 3;          // 0..127
            const int seg = e & 7;           // 16B segment in 128B row
            const uint32_t off = row * 128 + seg * 16;
            const uint32_t sw  = off ^ ((off >> 3) & 0x70);
            cp16(ts + sw, gb + (size_t)row * (KDIM * 2) + seg * 16);
        }
    }
    cp_commit();
}

__global__ void __launch_bounds__(256, 2)
tt_gemm_mma(const float* __restrict__ bias, float* __restrict__ out) {
    extern __shared__ __align__(128) char smem[];
    const uint32_t sb = smem_u32(smem);
    const int tid = threadIdx.x;
    const int lane = tid & 31;
    const int wid = tid >> 5;
    const int warpM = wid >> 2;      // 0..1
    const int warpN = wid & 3;       // 0..3
    const int bn = blockIdx.x, bm = blockIdx.y;

    float acc[4][4][4];
#pragma unroll
    for (int i = 0; i < 4; ++i)
#pragma unroll
        for (int j = 0; j < 4; ++j)
#pragma unroll
            for (int k = 0; k < 4; ++k) acc[i][j][k] = 0.f;

    // SW128: store XORs addr bits 4-6 with row bits 0-2. All row terms other
    // than (lane&7) are multiples of 8 -> load-side sw = (lane&7)<<4.
    const uint32_t sw = (uint32_t)((lane & 7) << 4);
    // A: row = warpM*64 + (lane&15) (+ mt*16); colB = (lane>>4)*16 (+ ks*32)
    const uint32_t aRowOff = (uint32_t)(warpM * 64 + (lane & 15)) * 128;
    const uint32_t aColB   = (uint32_t)((lane >> 4) << 4);
    // B: row = warpN*32 + (lane&7) + ((lane>>4)&1)*8 (+ np*16); colB = ((lane>>3)&1)*16
    const uint32_t bRowOff =
        (uint32_t)(warpN * 32 + (lane & 7) + ((lane >> 4) & 1) * 8) * 128;
    const uint32_t bColB = (uint32_t)(((lane >> 3) & 1) << 4);

    load_chunk(sb, 0, 0, bm, bn, tid);
    load_chunk(sb, 1, 1, bm, bn, tid);

    const int KT = KDIM / 64;  // 64
    int st = 0;
    for (int c = 0; c < KT; ++c) {
        if (c + 1 < KT) asm volatile("cp.async.wait_group 1;" ::: "memory");
        else            asm volatile("cp.async.wait_group 0;" ::: "memory");
        __syncthreads();

        if (c + 2 < KT) {
            int st2 = st + 2; if (st2 >= NSTAGE) st2 -= NSTAGE;
            load_chunk(sb, st2, c + 2, bm, bn, tid);
        }

        const uint32_t sA = sb + st * STAGE_BYTES;
        const uint32_t sB = sA + TILE_BYTES;

#pragma unroll
        for (int ks = 0; ks < 4; ++ks) {
            const uint32_t aco = (aColB + ks * 32) ^ sw;
            const uint32_t bco = (bColB + ks * 32) ^ sw;

            // B fragments for this k-step: 8 regs
            uint32_t bw[4][2];
#pragma unroll
            for (int np = 0; np < 2; ++np) {
                const uint32_t no = bRowOff + np * 16 * 128 + bco;
                uint32_t r0, r1, r2, r3;
                ldm4(r0, r1, r2, r3, sB + no);
                bw[np * 2][0] = r0; bw[np * 2][1] = r1;
                bw[np * 2 + 1][0] = r2; bw[np * 2 + 1][1] = r3;
            }

#pragma unroll
            for (int mt = 0; mt < 4; ++mt) {
                uint32_t ah[4];
                ldm4(ah[0], ah[1], ah[2], ah[3],
                     sA + aRowOff + mt * 16 * 128 + aco);
#pragma unroll
                for (int nt = 0; nt < 4; ++nt)
                    mma16816(acc[mt][nt], ah, bw[nt]);
            }
        }

        st = (st + 1 == NSTAGE) ? 0 : st + 1;
    }

    // Epilogue: c-frag layout m16n8: lane -> rows l/4, l/4+8; cols 2*(l%4)
    const int rbase = bm * 128 + warpM * 64 + (lane >> 2);
    const int cbase = bn * 128 + warpN * 32 + (lane & 3) * 2;
#pragma unroll
    for (int nt = 0; nt < 4; ++nt) {
        const int col = cbase + nt * 8;
        const float b0 = bias[col], b1 = bias[col + 1];
#pragma unroll
        for (int mt = 0; mt < 4; ++mt) {
            const int row = rbase + mt * 16;
            float2 v0 = make_float2(acc[mt][nt][0] + b0, acc[mt][nt][1] + b1);
            float2 v1 = make_float2(acc[mt][nt][2] + b0, acc[mt][nt][3] + b1);
            *(float2*)(out + (size_t)row * NDIM + col) = v0;
            *(float2*)(out + (size_t)(row + 8) * NDIM + col) = v1;
        }
    }
}

// ---------------------------------------------------------------------------
extern "C" void kernel_launch(void* const* d_in, const int* in_sizes, int n_in,
                              void* d_out, int out_size) {
    const float* x     = (const float*)d_in[0];
    const float* core0 = (const float*)d_in[1];
    const float* core1 = (const float*)d_in[2];
    const float* core2 = (const float*)d_in[3];
    const float* bias  = (const float*)d_in[4];
    float* out = (float*)d_out;

    cudaFuncSetAttribute(tt_gemm_mma,
                         cudaFuncAttributeMaxDynamicSharedMemorySize,
                         SMEM_TOTAL);

    tt_prep<<<8192, 256>>>(x, core0, core1, core2);

    dim3 grid(NDIM / 128, MDIM / 128);  // (32, 16)
    tt_gemm_mma<<<grid, 256, SMEM_TOTAL>>>(bias, out);
}

// round 11
// speedup vs baseline: 7.3203x; 1.0045x over previous
#include <cuda_runtime.h>
#include <cuda_fp16.h>
#include <cstdint>

// TensorTrainLinear: out = x @ W + bias.
// W (4096x4096) materialized from TT cores each launch, stored fp16 [o][in].
// Single-product fp16 GEMM (out = fp16(x) @ fp16(W) + bias, fp32 accum),
// rel_err 2.9e-4 < 1e-3.
// R11: (1) GEMM prefetch split around ks=0 so the LDGSTS burst doesn't
//      collide with the post-barrier LDSM/MMA ramp.
//      (2) prep: fatter x-convert blocks (2048 x 16 floats), W-build FMA
//      chains split into two partials.

#define KDIM 4096
#define NDIM 4096
#define MDIM 2048

// ---- device scratch (no runtime allocation allowed) ----
__device__ __half g_xh[(size_t)MDIM * KDIM];             // 16 MB
__device__ __half g_wt[(size_t)NDIM * KDIM];             // 32 MB  [o][in]

// ---------------------------------------------------------------------------
// helpers
// ---------------------------------------------------------------------------
__device__ __forceinline__ uint32_t smem_u32(const void* p) {
    uint32_t a;
    asm("{ .reg .u64 t; cvta.to.shared.u64 t, %1; cvt.u32.u64 %0, t; }"
        : "=r"(a) : "l"(p));
    return a;
}

__device__ __forceinline__ void cp16(uint32_t saddr, const void* gaddr) {
    asm volatile("cp.async.cg.shared.global [%0], [%1], 16;\n"
                 :: "r"(saddr), "l"(gaddr));
}
__device__ __forceinline__ void cp_commit() {
    asm volatile("cp.async.commit_group;\n" ::: "memory");
}

__device__ __forceinline__ void ldm4(uint32_t& r0, uint32_t& r1,
                                     uint32_t& r2, uint32_t& r3,
                                     uint32_t addr) {
    asm volatile("ldmatrix.sync.aligned.m8n8.x4.shared.b16 {%0,%1,%2,%3}, [%4];"
                 : "=r"(r0), "=r"(r1), "=r"(r2), "=r"(r3) : "r"(addr));
}

__device__ __forceinline__ void mma16816(float* c, const uint32_t* a,
                                         const uint32_t* b) {
    asm volatile(
        "mma.sync.aligned.m16n8k16.row.col.f32.f16.f16.f32 "
        "{%0,%1,%2,%3}, {%4,%5,%6,%7}, {%8,%9}, {%0,%1,%2,%3};"
        : "+f"(c[0]), "+f"(c[1]), "+f"(c[2]), "+f"(c[3])
        : "r"(a[0]), "r"(a[1]), "r"(a[2]), "r"(a[3]), "r"(b[0]), "r"(b[1]));
}

// ---------------------------------------------------------------------------
// Fused prep: blocks [0,2048): x -> fp16 (16 floats/thread).
//             blocks [2048,6144): W build (core chain contraction in smem).
// ---------------------------------------------------------------------------
__global__ __launch_bounds__(256) void tt_prep(const float* __restrict__ x,
                                               const float* __restrict__ core0,
                                               const float* __restrict__ core1,
                                               const float* __restrict__ core2) {
    const int tid = threadIdx.x;

    if (blockIdx.x < 2048) {
        // ---- x conversion: 16 floats per thread ----
        const size_t base = ((size_t)blockIdx.x * 256 + tid) * 16;
#pragma unroll
        for (int h = 0; h < 2; ++h) {
            const size_t b8 = base + h * 8;
            float4 v0 = *(const float4*)(x + b8);
            float4 v1 = *(const float4*)(x + b8 + 4);
            float f[8] = {v0.x, v0.y, v0.z, v0.w, v1.x, v1.y, v1.z, v1.w};
            __half hh[8];
#pragma unroll
            for (int i = 0; i < 8; ++i) hh[i] = __float2half(f[i]);
            *(uint4*)(g_xh + b8) = *(uint4*)hh;
        }
        return;
    }

    // ---- W build ----
    __shared__ float s_c2t[4096];   // [r][o3][i3]
    __shared__ float s_m01[256];    // [i2][r]
    __shared__ float s_c0[16];

    const int b   = blockIdx.x - 2048;     // 0..4095
    const int ohi = b >> 4;                // o1*16 + o2
    const int o2  = ohi & 15;
    const int i1  = b & 15;

    // core2 transposed into smem: src = r*256 + i3*16 + o3 -> [r][o3][i3]
#pragma unroll
    for (int i = 0; i < 16; ++i) {
        const int idx = tid + i * 256;
        const int r = idx >> 8, i3s = (idx >> 4) & 15, o3s = idx & 15;
        s_c2t[r * 256 + o3s * 16 + i3s] = core2[idx];
    }
    if (tid < 16) s_c0[tid] = core0[i1 * 256 + (ohi >> 4) * 16 + tid];
    __syncthreads();

    // M01 slice: thread tid = i2*16 + r  (two partial chains)
    {
        const int i2s = tid >> 4, r = tid & 15;
        const float* c1p = core1 + i2s * 256 + o2 * 16 + r;
        float a0 = 0.f, a1 = 0.f;
#pragma unroll
        for (int q = 0; q < 16; q += 2) {
            a0 = fmaf(s_c0[q],     c1p[q * 4096],       a0);
            a1 = fmaf(s_c0[q + 1], c1p[(q + 1) * 4096], a1);
        }
        s_m01[tid] = a0 + a1;
    }
    __syncthreads();

    const int i2 = tid >> 4, i3 = tid & 15;
    const int in = i1 * 256 + i2 * 16 + i3;
    float m01[16];
#pragma unroll
    for (int r = 0; r < 16; ++r) m01[r] = s_m01[i2 * 16 + r];

#pragma unroll
    for (int o3 = 0; o3 < 16; ++o3) {
        float a0 = 0.f, a1 = 0.f;
        const float* c2p = s_c2t + o3 * 16 + i3;
#pragma unroll
        for (int r = 0; r < 16; r += 2) {
            a0 = fmaf(m01[r],     c2p[r * 256],       a0);
            a1 = fmaf(m01[r + 1], c2p[(r + 1) * 256], a1);
        }
        g_wt[(size_t)(ohi * 16 + o3) * KDIM + in] = __float2half(a0 + a1);
    }
}

// ---------------------------------------------------------------------------
// GEMM: out[2048,4096] = xh @ W16 + bias via mma.sync fp16, single product.
// CTA 128x128, BK=64, 8 warps (2x4), warp tile 64x32, 2 CTAs/SM.
// 128B rows, SW128 swizzle (off ^ ((off>>3)&0x70)); 3-stage pipeline,
// one __syncthreads per iteration; prefetch split: A-tile after barrier,
// B-tile (+commit) after ks=0.
// ---------------------------------------------------------------------------
#define TILE_BYTES  16384              // 128 rows x 128B
#define STAGE_BYTES (2 * TILE_BYTES)   // 32768 (A, B)
#define NSTAGE      3
#define SMEM_TOTAL  (NSTAGE * STAGE_BYTES)  // 98304

// Load one 128x64 fp16 tile (A: t=0 from g_xh row bm*128; B: t=1 from g_wt
// row bn*128) into stage, SW128-swizzled.
__device__ __forceinline__ void load_tile(uint32_t sb, int stage, int t,
                                          int c, int blk, int tid) {
    const __half* gbase =
        (t == 0 ? g_xh + ((size_t)blk * 128) * KDIM
                : g_wt + ((size_t)blk * 128) * KDIM) + (size_t)c * 64;
    const uint32_t ts = sb + stage * STAGE_BYTES + t * TILE_BYTES;
    const char* gb = (const char*)gbase;
#pragma unroll
    for (int i = 0; i < 4; ++i) {
        const int e   = tid + i * 256;   // 0..1023
        const int row = e >> 3;          // 0..127
        const int seg = e & 7;           // 16B segment in 128B row
        const uint32_t off = row * 128 + seg * 16;
        const uint32_t sw  = off ^ ((off >> 3) & 0x70);
        cp16(ts + sw, gb + (size_t)row * (KDIM * 2) + seg * 16);
    }
}

__global__ void __launch_bounds__(256, 2)
tt_gemm_mma(const float* __restrict__ bias, float* __restrict__ out) {
    extern __shared__ __align__(128) char smem[];
    const uint32_t sb = smem_u32(smem);
    const int tid = threadIdx.x;
    const int lane = tid & 31;
    const int wid = tid >> 5;
    const int warpM = wid >> 2;      // 0..1
    const int warpN = wid & 3;       // 0..3
    const int bn = blockIdx.x, bm = blockIdx.y;

    float acc[4][4][4];
#pragma unroll
    for (int i = 0; i < 4; ++i)
#pragma unroll
        for (int j = 0; j < 4; ++j)
#pragma unroll
            for (int k = 0; k < 4; ++k) acc[i][j][k] = 0.f;

    // SW128: store XORs addr bits 4-6 with row bits 0-2. Load-side:
    // sw = (lane&7) << 4 (all other row terms are multiples of 8).
    const uint32_t sw = (uint32_t)((lane & 7) << 4);
    const uint32_t aRowOff = (uint32_t)(warpM * 64 + (lane & 15)) * 128;
    const uint32_t aColB   = (uint32_t)((lane >> 4) << 4);
    const uint32_t bRowOff =
        (uint32_t)(warpN * 32 + (lane & 7) + ((lane >> 4) & 1) * 8) * 128;
    const uint32_t bColB = (uint32_t)(((lane >> 3) & 1) << 4);

    load_tile(sb, 0, 0, 0, bm, tid);
    load_tile(sb, 0, 1, 0, bn, tid);
    cp_commit();
    load_tile(sb, 1, 0, 1, bm, tid);
    load_tile(sb, 1, 1, 1, bn, tid);
    cp_commit();

    const int KT = KDIM / 64;  // 64
    int st = 0;
    for (int c = 0; c < KT; ++c) {
        if (c + 1 < KT) asm volatile("cp.async.wait_group 1;" ::: "memory");
        else            asm volatile("cp.async.wait_group 0;" ::: "memory");
        __syncthreads();

        const bool pf = (c + 2 < KT);
        int st2 = st + 2; if (st2 >= NSTAGE) st2 -= NSTAGE;

        // A-half of prefetch right after barrier
        if (pf) load_tile(sb, st2, 0, c + 2, bm, tid);

        const uint32_t sA = sb + st * STAGE_BYTES;
        const uint32_t sB = sA + TILE_BYTES;

#pragma unroll
        for (int ks = 0; ks < 4; ++ks) {
            const uint32_t aco = (aColB + ks * 32) ^ sw;
            const uint32_t bco = (bColB + ks * 32) ^ sw;

            uint32_t bw[4][2];
#pragma unroll
            for (int np = 0; np < 2; ++np) {
                const uint32_t no = bRowOff + np * 16 * 128 + bco;
                uint32_t r0, r1, r2, r3;
                ldm4(r0, r1, r2, r3, sB + no);
                bw[np * 2][0] = r0; bw[np * 2][1] = r1;
                bw[np * 2 + 1][0] = r2; bw[np * 2 + 1][1] = r3;
            }

#pragma unroll
            for (int mt = 0; mt < 4; ++mt) {
                uint32_t ah[4];
                ldm4(ah[0], ah[1], ah[2], ah[3],
                     sA + aRowOff + mt * 16 * 128 + aco);
#pragma unroll
                for (int nt = 0; nt < 4; ++nt)
                    mma16816(acc[mt][nt], ah, bw[nt]);
            }

            // B-half of prefetch + commit after first k-step
            if (ks == 0 && pf) {
                load_tile(sb, st2, 1, c + 2, bn, tid);
                cp_commit();
            }
        }

        st = (st + 1 == NSTAGE) ? 0 : st + 1;
    }

    // Epilogue: c-frag layout m16n8: lane -> rows l/4, l/4+8; cols 2*(l%4)
    const int rbase = bm * 128 + warpM * 64 + (lane >> 2);
    const int cbase = bn * 128 + warpN * 32 + (lane & 3) * 2;
#pragma unroll
    for (int nt = 0; nt < 4; ++nt) {
        const int col = cbase + nt * 8;
        const float b0 = bias[col], b1 = bias[col + 1];
#pragma unroll
        for (int mt = 0; mt < 4; ++mt) {
            const int row = rbase + mt * 16;
            float2 v0 = make_float2(acc[mt][nt][0] + b0, acc[mt][nt][1] + b1);
            float2 v1 = make_float2(acc[mt][nt][2] + b0, acc[mt][nt][3] + b1);
            *(float2*)(out + (size_t)row * NDIM + col) = v0;
            *(float2*)(out + (size_t)(row + 8) * NDIM + col) = v1;
        }
    }
}

// ---------------------------------------------------------------------------
extern "C" void kernel_launch(void* const* d_in, const int* in_sizes, int n_in,
                              void* d_out, int out_size) {
    const float* x     = (const float*)d_in[0];
    const float* core0 = (const float*)d_in[1];
    const float* core1 = (const float*)d_in[2];
    const float* core2 = (const float*)d_in[3];
    const float* bias  = (const float*)d_in[4];
    float* out = (float*)d_out;

    cudaFuncSetAttribute(tt_gemm_mma,
                         cudaFuncAttributeMaxDynamicSharedMemorySize,
                         SMEM_TOTAL);

    tt_prep<<<6144, 256>>>(x, core0, core1, core2);

    dim3 grid(NDIM / 128, MDIM / 128);  // (32, 16)
    tt_gemm_mma<<<grid, 256, SMEM_TOTAL>>>(bias, out);
}